// round 1
// baseline (speedup 1.0000x reference)
#include <cuda_runtime.h>

#define NB 128
#define CD 256
#define KK 64
#define PT 1024

// Scratch (no allocations allowed -> device globals)
__device__ float g_inv[NB * PT];             // 0.5 MB  per-pixel 1/||x||
__device__ float g_at[(size_t)NB * PT * KK]; // 32 MB   a*inv, layout [n][p][k]
__device__ float g_agg[(size_t)NB * KK * CD];// 8 MB    agg [n][k][c]
__device__ float g_asum[NB * KK];
__device__ float g_nsum[NB];

// ---------------- K0: zero accumulators (must run every replay) ---------------
__global__ void k_zero() {
    int t = threadIdx.x;
    for (int i = t; i < NB * KK; i += 256) g_asum[i] = 0.f;
    if (t < NB) g_nsum[t] = 0.f;
}

// ---------------- K1: per-pixel inverse norm ----------------------------------
__global__ void k_inv(const float* __restrict__ x) {
    int n = blockIdx.y;
    int p = blockIdx.x * 256 + threadIdx.x;
    const float* xp = x + (size_t)n * CD * PT + p;
    float s0 = 0.f, s1 = 0.f, s2 = 0.f, s3 = 0.f;
#pragma unroll 8
    for (int c = 0; c < CD; c += 4) {
        float v0 = xp[(size_t)c * PT];
        float v1 = xp[(size_t)(c + 1) * PT];
        float v2 = xp[(size_t)(c + 2) * PT];
        float v3 = xp[(size_t)(c + 3) * PT];
        s0 += v0 * v0; s1 += v1 * v1; s2 += v2 * v2; s3 += v3 * v3;
    }
    float s = (s0 + s1) + (s2 + s3);
    g_inv[n * PT + p] = 1.0f / fmaxf(sqrtf(s), 1e-12f);
}

// ---------------- K2: GEMM1 (logits) + fused softmax + asum -------------------
// Block: (ptile=128, n). 256 threads. Thread tile 8k x 4p.
// kg = t&7 (8 groups of 8 k), pg = t>>3 (32 groups of 4 p).
#define WS_S 68
#define XS_S 132
__global__ __launch_bounds__(256) void k_gemm1(const float* __restrict__ x,
                                               const float* __restrict__ w,
                                               const float* __restrict__ b) {
    __shared__ float Ws[32 * WS_S];   // [ci][k], padded
    __shared__ float Xs[32 * XS_S];   // [ci][p], padded
    __shared__ float s_asum[KK];

    const int n  = blockIdx.y;
    const int p0 = blockIdx.x * 128;
    const int t  = threadIdx.x;
    const int kg = t & 7;
    const int pg = t >> 3;

    if (t < KK) s_asum[t] = 0.f;

    float acc[8][4];
#pragma unroll
    for (int j = 0; j < 8; j++)
#pragma unroll
        for (int jp = 0; jp < 4; jp++) acc[j][jp] = 0.f;

    const size_t xbase = (size_t)n * CD * PT;

    for (int c0 = 0; c0 < CD; c0 += 32) {
        __syncthreads();
        // load W chunk transposed: Ws[ci][k] = w[k][c0+ci]
#pragma unroll
        for (int i = 0; i < 8; i++) {
            int idx = t + i * 256;
            int ci = idx & 31, k = idx >> 5;
            Ws[ci * WS_S + k] = w[k * CD + c0 + ci];
        }
        // load X chunk: Xs[ci][pi], float4
#pragma unroll
        for (int i = 0; i < 4; i++) {
            int idx = t + i * 256;
            int p4 = idx & 31, ci = idx >> 5;
            float4 v = *reinterpret_cast<const float4*>(
                x + xbase + (size_t)(c0 + ci) * PT + p0 + p4 * 4);
            *reinterpret_cast<float4*>(&Xs[ci * XS_S + p4 * 4]) = v;
        }
        __syncthreads();
#pragma unroll
        for (int ci = 0; ci < 32; ci++) {
            float4 w0 = *reinterpret_cast<const float4*>(&Ws[ci * WS_S + kg * 8]);
            float4 w1 = *reinterpret_cast<const float4*>(&Ws[ci * WS_S + kg * 8 + 4]);
            float4 xv = *reinterpret_cast<const float4*>(&Xs[ci * XS_S + pg * 4]);
            float wv[8] = {w0.x, w0.y, w0.z, w0.w, w1.x, w1.y, w1.z, w1.w};
            float xa[4] = {xv.x, xv.y, xv.z, xv.w};
#pragma unroll
            for (int j = 0; j < 8; j++)
#pragma unroll
                for (int jp = 0; jp < 4; jp++) acc[j][jp] += wv[j] * xa[jp];
        }
    }

    // ---- epilogue: logits -> softmax over k (64) -> a, a*inv, asum ----
    const int pbase = p0 + pg * 4;
    float inv[4], bias[8];
#pragma unroll
    for (int jp = 0; jp < 4; jp++) inv[jp] = g_inv[n * PT + pbase + jp];
#pragma unroll
    for (int j = 0; j < 8; j++) bias[j] = b[kg * 8 + j];

#pragma unroll
    for (int j = 0; j < 8; j++)
#pragma unroll
        for (int jp = 0; jp < 4; jp++) acc[j][jp] = acc[j][jp] * inv[jp] + bias[j];

    float m[4];
#pragma unroll
    for (int jp = 0; jp < 4; jp++) {
        float mm = acc[0][jp];
#pragma unroll
        for (int j = 1; j < 8; j++) mm = fmaxf(mm, acc[j][jp]);
        m[jp] = mm;
    }
#pragma unroll
    for (int msk = 1; msk <= 4; msk <<= 1)
#pragma unroll
        for (int jp = 0; jp < 4; jp++)
            m[jp] = fmaxf(m[jp], __shfl_xor_sync(0xffffffffu, m[jp], msk));

    float s[4] = {0.f, 0.f, 0.f, 0.f};
#pragma unroll
    for (int j = 0; j < 8; j++)
#pragma unroll
        for (int jp = 0; jp < 4; jp++) {
            acc[j][jp] = __expf(acc[j][jp] - m[jp]);
            s[jp] += acc[j][jp];
        }
#pragma unroll
    for (int msk = 1; msk <= 4; msk <<= 1)
#pragma unroll
        for (int jp = 0; jp < 4; jp++)
            s[jp] += __shfl_xor_sync(0xffffffffu, s[jp], msk);
    float rs[4];
#pragma unroll
    for (int jp = 0; jp < 4; jp++) rs[jp] = 1.0f / s[jp];
#pragma unroll
    for (int j = 0; j < 8; j++)
#pragma unroll
        for (int jp = 0; jp < 4; jp++) acc[j][jp] *= rs[jp];  // acc = a

    // asum: reduce a over this warp's 16 pixels, one lane per kg adds
#pragma unroll
    for (int j = 0; j < 8; j++) {
        float tj = (acc[j][0] + acc[j][1]) + (acc[j][2] + acc[j][3]);
        tj += __shfl_xor_sync(0xffffffffu, tj, 8);
        tj += __shfl_xor_sync(0xffffffffu, tj, 16);
        if ((t & 31) < 8) atomicAdd(&s_asum[kg * 8 + j], tj);
    }

    // write a*inv in [n][p][k] layout (coalesced consumer in GEMM2)
#pragma unroll
    for (int jp = 0; jp < 4; jp++) {
        float iv = inv[jp];
        float4 o0 = make_float4(acc[0][jp] * iv, acc[1][jp] * iv,
                                acc[2][jp] * iv, acc[3][jp] * iv);
        float4 o1 = make_float4(acc[4][jp] * iv, acc[5][jp] * iv,
                                acc[6][jp] * iv, acc[7][jp] * iv);
        float* dst = &g_at[(size_t)n * PT * KK + (size_t)(pbase + jp) * KK + kg * 8];
        *reinterpret_cast<float4*>(dst) = o0;
        *reinterpret_cast<float4*>(dst + 4) = o1;
    }

    __syncthreads();
    if (t < KK) atomicAdd(&g_asum[n * KK + t], s_asum[t]);
}

// ---------------- K3: GEMM2  agg[k][c] = sum_p (a*inv)[k][p] * x[c][p] --------
// Block: (chalf, n). 256 threads. Out tile 64k x 128c, thread tile 8k x 4c.
#define AS_S 68
#define XS2_S 33
__global__ __launch_bounds__(256) void k_gemm2(const float* __restrict__ x) {
    __shared__ float As[32 * AS_S];    // [pi][k], padded
    __shared__ float Xs[128 * XS2_S];  // [ci][pi], padded

    const int n  = blockIdx.y;
    const int c0 = blockIdx.x * 128;
    const int t  = threadIdx.x;
    const int kg = t & 7;
    const int cg = t >> 3;

    float acc[8][4];
#pragma unroll
    for (int j = 0; j < 8; j++)
#pragma unroll
        for (int jc = 0; jc < 4; jc++) acc[j][jc] = 0.f;

    const size_t xbase = (size_t)n * CD * PT;
    const size_t abase = (size_t)n * PT * KK;

    for (int pc = 0; pc < PT; pc += 32) {
        __syncthreads();
        // As[pi][k] from g_at (coalesced rows of 64 floats)
#pragma unroll
        for (int i = 0; i < 2; i++) {
            int idx = t + i * 256;
            int k4 = idx & 15, pi = idx >> 4;
            float4 v = *reinterpret_cast<const float4*>(
                &g_at[abase + (size_t)(pc + pi) * KK + k4 * 4]);
            *reinterpret_cast<float4*>(&As[pi * AS_S + k4 * 4]) = v;
        }
        // Xs[ci][pi] from x (coalesced 128B rows)
#pragma unroll
        for (int i = 0; i < 16; i++) {
            int idx = t + i * 256;
            int pi = idx & 31, ci = idx >> 5;
            Xs[ci * XS2_S + pi] = x[xbase + (size_t)(c0 + ci) * PT + pc + pi];
        }
        __syncthreads();
#pragma unroll
        for (int pp = 0; pp < 32; pp++) {
            float4 a0 = *reinterpret_cast<const float4*>(&As[pp * AS_S + kg * 8]);
            float4 a1 = *reinterpret_cast<const float4*>(&As[pp * AS_S + kg * 8 + 4]);
            float av[8] = {a0.x, a0.y, a0.z, a0.w, a1.x, a1.y, a1.z, a1.w};
            float xv[4];
#pragma unroll
            for (int jc = 0; jc < 4; jc++) xv[jc] = Xs[(cg * 4 + jc) * XS2_S + pp];
#pragma unroll
            for (int j = 0; j < 8; j++)
#pragma unroll
                for (int jc = 0; jc < 4; jc++) acc[j][jc] += av[j] * xv[jc];
        }
    }

#pragma unroll
    for (int j = 0; j < 8; j++) {
        float4 v = make_float4(acc[j][0], acc[j][1], acc[j][2], acc[j][3]);
        *reinterpret_cast<float4*>(
            &g_agg[(size_t)n * KK * CD + (size_t)(kg * 8 + j) * CD + c0 + cg * 4]) = v;
    }
}

// ---------------- K4a: vlad = agg - asum*cent, intra-normalize ----------------
__global__ void k_vlad(const float* __restrict__ cent, float* __restrict__ out) {
    const int k = blockIdx.x;
    const int n = blockIdx.y;
    const int t = threadIdx.x;  // 256 = one c each
    float asum = g_asum[n * KK + k];
    float v = g_agg[(size_t)n * KK * CD + k * CD + t] - asum * cent[k * CD + t];
    float s = v * v;
#pragma unroll
    for (int m = 16; m; m >>= 1) s += __shfl_xor_sync(0xffffffffu, s, m);
    __shared__ float red[8];
    if ((t & 31) == 0) red[t >> 5] = s;
    __syncthreads();
    float tot = 0.f;
#pragma unroll
    for (int i = 0; i < 8; i++) tot += red[i];
    float denom = fmaxf(sqrtf(tot), 1e-12f);
    out[(size_t)n * KK * CD + k * CD + t] = v / denom;
    if (t == 0) atomicAdd(&g_nsum[n], tot / (denom * denom));
}

// ---------------- K4b: global L2 normalize per n ------------------------------
__global__ void k_final(float* __restrict__ out) {
    const int bx = blockIdx.x;           // 2048 blocks, 16 per n
    const int n  = bx >> 4;
    const size_t base = (size_t)bx * 1024 + threadIdx.x * 4;
    float r = 1.0f / fmaxf(sqrtf(g_nsum[n]), 1e-12f);
    float4 v = *reinterpret_cast<const float4*>(out + base);
    v.x *= r; v.y *= r; v.z *= r; v.w *= r;
    *reinterpret_cast<float4*>(out + base) = v;
}

// ------------------------------------------------------------------------------
extern "C" void kernel_launch(void* const* d_in, const int* in_sizes, int n_in,
                              void* d_out, int out_size) {
    const float* x    = (const float*)d_in[0];  // (128, 256, 32, 32)
    const float* w    = (const float*)d_in[1];  // (64, 256)
    const float* b    = (const float*)d_in[2];  // (64)
    const float* cent = (const float*)d_in[3];  // (64, 256)
    float* out = (float*)d_out;                 // (128, 16384)

    k_zero<<<1, 256>>>();
    k_inv<<<dim3(4, NB), 256>>>(x);
    k_gemm1<<<dim3(8, NB), 256>>>(x, w, b);
    k_gemm2<<<dim3(2, NB), 256>>>(x);
    k_vlad<<<dim3(KK, NB), 256>>>(cent, out);
    k_final<<<2048, 256>>>(out);
}

// round 4
// speedup vs baseline: 5.1942x; 5.1942x over previous
#include <cuda_runtime.h>
#include <cuda_bf16.h>
#include <cstdint>

#define NB 128
#define CD 256
#define KK 64
#define PT 1024

// ---- smem byte offsets ----
#define SM_X    0            // x tile bf16 [256 c][136 p] (stride 272 B)
#define XSTR    272
#define SM_W    69632        // W bf16 [64 k][264 c] (stride 528 B)
#define WSTR    528
#define SM_AT   103424       // at bf16 [64 k][136 p] (stride 272 B)
#define ASTR    272
#define SM_LOG  120832       // logits f32 [128 p][66]
#define LSTR    66
#define SM_INV  154624       // 128 f
#define SM_SQ   155136       // 128 x 8 f
#define SM_RED  159232       // 512 f
#define SM_ASUM 161280       // 64 f
#define SM_RK   161792       // 64 f
#define SM_BIAS 162048       // 64 f
#define SM_G2   162304       // 2 f
#define SM_TOTAL 162336

__device__ __forceinline__ uint32_t smem_u32(const void* p) {
    uint32_t a;
    asm("{ .reg .u64 t; cvta.to.shared.u64 t, %1; cvt.u32.u64 %0, t; }" : "=r"(a) : "l"(p));
    return a;
}
__device__ __forceinline__ uint32_t bf2(float lo, float hi) {
    uint32_t r;
    asm("cvt.rn.bf16x2.f32 %0, %1, %2;" : "=r"(r) : "f"(hi), "f"(lo));
    return r;
}
__device__ __forceinline__ void ldm4t(uint32_t* r, uint32_t addr) {
    asm volatile("ldmatrix.sync.aligned.m8n8.x4.trans.shared.b16 {%0,%1,%2,%3}, [%4];"
                 : "=r"(r[0]), "=r"(r[1]), "=r"(r[2]), "=r"(r[3]) : "r"(addr));
}
__device__ __forceinline__ void ldm4(uint32_t* r, uint32_t addr) {
    asm volatile("ldmatrix.sync.aligned.m8n8.x4.shared.b16 {%0,%1,%2,%3}, [%4];"
                 : "=r"(r[0]), "=r"(r[1]), "=r"(r[2]), "=r"(r[3]) : "r"(addr));
}
__device__ __forceinline__ void mma_bf16(float* d, const uint32_t* a, uint32_t b0, uint32_t b1) {
    asm volatile("mma.sync.aligned.m16n8k16.row.col.f32.bf16.bf16.f32 "
                 "{%0,%1,%2,%3}, {%4,%5,%6,%7}, {%8,%9}, {%0,%1,%2,%3};"
                 : "+f"(d[0]), "+f"(d[1]), "+f"(d[2]), "+f"(d[3])
                 : "r"(a[0]), "r"(a[1]), "r"(a[2]), "r"(a[3]), "r"(b0), "r"(b1));
}

__global__ __launch_bounds__(256, 1) void netvlad_mma(
    const float* __restrict__ x, const float* __restrict__ w,
    const float* __restrict__ b, const float* __restrict__ cent,
    float* __restrict__ out) {
    extern __shared__ char smem[];
    float* smf = (float*)smem;
    const uint32_t sb = smem_u32(smem);
    const int t = threadIdx.x, lane = t & 31, wp = t >> 5;
    const int n = blockIdx.x;
    const float* xn = x + (size_t)n * CD * PT;

    // ---- one-time: W -> bf16 smem, bias, asum=0 ----
#pragma unroll
    for (int i = 0; i < 32; i++) {
        int id2 = t + (i << 8);                 // float2 index over 64x256
        int kk = id2 >> 7, c2 = id2 & 127;
        float2 v = ((const float2*)w)[id2];
        *(uint32_t*)(smem + SM_W + kk * WSTR + c2 * 4) = bf2(v.x, v.y);
    }
    if (t < KK) { smf[(SM_BIAS >> 2) + t] = b[t]; smf[(SM_ASUM >> 2) + t] = 0.f; }
    __syncthreads();

    float agg[4][4][4];
#pragma unroll
    for (int i = 0; i < 4; i++)
#pragma unroll
        for (int j = 0; j < 4; j++)
#pragma unroll
            for (int q = 0; q < 4; q++) agg[i][j][q] = 0.f;

    const int la = lane & 7, grp = lane >> 3;

    for (int tl = 0; tl < 8; tl++) {
        const int p0 = tl * 128;

        // ---- phase A: x -> bf16 smem + square partials ----
        {
            const int pq = t & 31, cb = t >> 5;
            const float* xp = xn + p0 + pq * 4;
            float s0 = 0.f, s1 = 0.f, s2 = 0.f, s3 = 0.f;
#pragma unroll
            for (int i = 0; i < 32; i++) {
                int c = cb + (i << 3);
                float4 v = *(const float4*)(xp + (size_t)c * PT);
                s0 += v.x * v.x; s1 += v.y * v.y; s2 += v.z * v.z; s3 += v.w * v.w;
                uint2 u = make_uint2(bf2(v.x, v.y), bf2(v.z, v.w));
                *(uint2*)(smem + SM_X + c * XSTR + pq * 8) = u;
            }
            float* sq = smf + (SM_SQ >> 2) + pq * 32 + cb;
            sq[0] = s0; sq[8] = s1; sq[16] = s2; sq[24] = s3;
        }
        __syncthreads();
        if (t < 128) {
            const float* sq = smf + (SM_SQ >> 2) + t * 8;
            float q = 0.f;
#pragma unroll
            for (int i = 0; i < 8; i++) q += sq[i];
            smf[(SM_INV >> 2) + t] = 1.0f / fmaxf(sqrtf(q), 1e-12f);
        }
        __syncthreads();

        // ---- phase C: GEMM1 logits[p][k] = x^T W^T ----
        {
            const int mg = wp >> 2, ng = wp & 3;
            float acc[4][2][4];
#pragma unroll
            for (int i = 0; i < 4; i++)
#pragma unroll
                for (int j = 0; j < 2; j++)
#pragma unroll
                    for (int q = 0; q < 4; q++) acc[i][j][q] = 0.f;
#pragma unroll
            for (int ks = 0; ks < 16; ks++) {
                const int cbase = ks * 16;
                uint32_t bb[2][2];
#pragma unroll
                for (int nt = 0; nt < 2; nt++) {
                    int kk = (ng * 2 + nt) * 8 + (lane >> 2);
                    const char* wr = smem + SM_W + kk * WSTR + (cbase + ((lane & 3) << 1)) * 2;
                    bb[nt][0] = *(const uint32_t*)wr;
                    bb[nt][1] = *(const uint32_t*)(wr + 16);
                }
                const int cA = cbase + la + ((grp >> 1) << 3);
#pragma unroll
                for (int mt = 0; mt < 4; mt++) {
                    int pA = (mg * 4 + mt) * 16 + ((grp & 1) << 3);
                    uint32_t af[4];
                    ldm4t(af, sb + SM_X + cA * XSTR + pA * 2);
                    mma_bf16(acc[mt][0], af, bb[0][0], bb[0][1]);
                    mma_bf16(acc[mt][1], af, bb[1][0], bb[1][1]);
                }
            }
#pragma unroll
            for (int mt = 0; mt < 4; mt++)
#pragma unroll
                for (int nt = 0; nt < 2; nt++) {
                    int p = (mg * 4 + mt) * 16 + (lane >> 2);
                    int k = (ng * 2 + nt) * 8 + ((lane & 3) << 1);
                    *(float2*)(smem + SM_LOG + (p * LSTR + k) * 4) =
                        make_float2(acc[mt][nt][0], acc[mt][nt][1]);
                    *(float2*)(smem + SM_LOG + ((p + 8) * LSTR + k) * 4) =
                        make_float2(acc[mt][nt][2], acc[mt][nt][3]);
                }
        }
        __syncthreads();

        // ---- phase D: softmax (2 threads per pixel), at = a*inv, asum partials ----
        {
            const int p = t >> 1, kh = t & 1;
            const float invp = smf[(SM_INV >> 2) + p];
            float lg[32];
            const float2* lp = (const float2*)(smem + SM_LOG + (p * LSTR + kh * 32) * 4);
#pragma unroll
            for (int j = 0; j < 16; j++) {
                float2 v = lp[j];
                lg[2 * j] = v.x; lg[2 * j + 1] = v.y;
            }
            float mx = -1e30f;
#pragma unroll
            for (int j = 0; j < 32; j++) {
                lg[j] = lg[j] * invp + smf[(SM_BIAS >> 2) + kh * 32 + j];
                mx = fmaxf(mx, lg[j]);
            }
            mx = fmaxf(mx, __shfl_xor_sync(0xffffffffu, mx, 1));
            float sum = 0.f;
#pragma unroll
            for (int j = 0; j < 32; j++) { lg[j] = __expf(lg[j] - mx); sum += lg[j]; }
            sum += __shfl_xor_sync(0xffffffffu, sum, 1);
            const float rs = 1.0f / sum, rsv = rs * invp;
#pragma unroll
            for (int j = 0; j < 32; j++) {
                float a = lg[j] * rs;
                float v = a;
                v += __shfl_xor_sync(0xffffffffu, v, 2);
                v += __shfl_xor_sync(0xffffffffu, v, 4);
                v += __shfl_xor_sync(0xffffffffu, v, 8);
                v += __shfl_xor_sync(0xffffffffu, v, 16);
                if (lane < 2) smf[(SM_RED >> 2) + wp * 64 + lane * 32 + j] = v;
                *(__nv_bfloat16*)(smem + SM_AT + (kh * 32 + j) * ASTR + p * 2) =
                    __float2bfloat16(lg[j] * rsv);
            }
        }
        __syncthreads();

        // ---- asum fold (warps 0-1) + phase E: GEMM2 agg[k][c] += at @ x^T ----
        if (t < 64) {
            float s = 0.f;
#pragma unroll
            for (int i = 0; i < 8; i++) s += smf[(SM_RED >> 2) + i * 64 + t];
            smf[(SM_ASUM >> 2) + t] += s;
        }
        {
            const int cwb = wp * 32;
#pragma unroll
            for (int ks = 0; ks < 8; ks++) {
                const int pb = ks * 16;
                uint32_t af[4][4];
#pragma unroll
                for (int mt = 0; mt < 4; mt++) {
                    int kR = mt * 16 + la + ((grp & 1) << 3);
                    int pA = pb + ((grp >> 1) << 3);
                    ldm4(af[mt], sb + SM_AT + kR * ASTR + pA * 2);
                }
#pragma unroll
                for (int nt = 0; nt < 4; nt++) {
                    int c = cwb + nt * 8 + (lane >> 2);
                    const char* xr = smem + SM_X + c * XSTR + (pb + ((lane & 3) << 1)) * 2;
                    uint32_t b0 = *(const uint32_t*)xr;
                    uint32_t b1 = *(const uint32_t*)(xr + 16);
#pragma unroll
                    for (int mt = 0; mt < 4; mt++) mma_bf16(agg[mt][nt], af[mt], b0, b1);
                }
            }
        }
        __syncthreads();
    }

    // ---- epilogue: vlad = agg - asum*cent, intra-norm, global norm, store ----
#pragma unroll
    for (int mt = 0; mt < 4; mt++) {
        int k0 = mt * 16 + (lane >> 2);
        float as0 = smf[(SM_ASUM >> 2) + k0];
        float as1 = smf[(SM_ASUM >> 2) + k0 + 8];
#pragma unroll
        for (int nt = 0; nt < 4; nt++) {
            int c0 = wp * 32 + nt * 8 + ((lane & 3) << 1);
            float2 ce0 = *(const float2*)(cent + k0 * CD + c0);
            float2 ce1 = *(const float2*)(cent + (k0 + 8) * CD + c0);
            agg[mt][nt][0] -= as0 * ce0.x;
            agg[mt][nt][1] -= as0 * ce0.y;
            agg[mt][nt][2] -= as1 * ce1.x;
            agg[mt][nt][3] -= as1 * ce1.y;
        }
    }
#pragma unroll
    for (int mt = 0; mt < 4; mt++) {
        float sA = 0.f, sB = 0.f;
#pragma unroll
        for (int nt = 0; nt < 4; nt++) {
            sA += agg[mt][nt][0] * agg[mt][nt][0] + agg[mt][nt][1] * agg[mt][nt][1];
            sB += agg[mt][nt][2] * agg[mt][nt][2] + agg[mt][nt][3] * agg[mt][nt][3];
        }
        sA += __shfl_xor_sync(0xffffffffu, sA, 1);
        sA += __shfl_xor_sync(0xffffffffu, sA, 2);
        sB += __shfl_xor_sync(0xffffffffu, sB, 1);
        sB += __shfl_xor_sync(0xffffffffu, sB, 2);
        if ((lane & 3) == 0) {
            smf[(SM_RED >> 2) + (mt * 16 + (lane >> 2)) * 8 + wp] = sA;
            smf[(SM_RED >> 2) + (mt * 16 + 8 + (lane >> 2)) * 8 + wp] = sB;
        }
    }
    __syncthreads();
    if (t < 64) {
        float ss = 0.f;
#pragma unroll
        for (int i = 0; i < 8; i++) ss += smf[(SM_RED >> 2) + t * 8 + i];
        float dk = fmaxf(sqrtf(ss), 1e-12f);
        smf[(SM_RK >> 2) + t] = 1.0f / dk;
        float gp = ss / (dk * dk);
        gp += __shfl_xor_sync(0xffffffffu, gp, 16);
        gp += __shfl_xor_sync(0xffffffffu, gp, 8);
        gp += __shfl_xor_sync(0xffffffffu, gp, 4);
        gp += __shfl_xor_sync(0xffffffffu, gp, 2);
        gp += __shfl_xor_sync(0xffffffffu, gp, 1);
        if (lane == 0) smf[(SM_G2 >> 2) + wp] = gp;
    }
    __syncthreads();
    const float rg = 1.0f / fmaxf(sqrtf(smf[SM_G2 >> 2] + smf[(SM_G2 >> 2) + 1]), 1e-12f);
    float* on = out + (size_t)n * KK * CD;
#pragma unroll
    for (int mt = 0; mt < 4; mt++) {
        int k0 = mt * 16 + (lane >> 2);
        float r0 = smf[(SM_RK >> 2) + k0] * rg;
        float r1 = smf[(SM_RK >> 2) + k0 + 8] * rg;
#pragma unroll
        for (int nt = 0; nt < 4; nt++) {
            int c0 = wp * 32 + nt * 8 + ((lane & 3) << 1);
            *(float2*)(on + k0 * CD + c0) =
                make_float2(agg[mt][nt][0] * r0, agg[mt][nt][1] * r0);
            *(float2*)(on + (k0 + 8) * CD + c0) =
                make_float2(agg[mt][nt][2] * r1, agg[mt][nt][3] * r1);
        }
    }
}

// ------------------------------------------------------------------------------
extern "C" void kernel_launch(void* const* d_in, const int* in_sizes, int n_in,
                              void* d_out, int out_size) {
    const float* x    = (const float*)d_in[0];  // (128, 256, 32, 32)
    const float* w    = (const float*)d_in[1];  // (64, 256)
    const float* b    = (const float*)d_in[2];  // (64)
    const float* cent = (const float*)d_in[3];  // (64, 256)
    float* out = (float*)d_out;                 // (128, 16384)

    cudaFuncSetAttribute(netvlad_mma, cudaFuncAttributeMaxDynamicSharedMemorySize, SM_TOTAL);
    netvlad_mma<<<NB, 256, SM_TOTAL>>>(x, w, b, cent, out);
}

// round 5
// speedup vs baseline: 5.3526x; 1.0305x over previous
#include <cuda_runtime.h>
#include <cuda_bf16.h>
#include <cstdint>

#define NB 128
#define CD 256
#define KK 64
#define PT 1024

// ---- smem byte offsets ----
#define SM_X    0            // x tile bf16 [256 c][136 p] (stride 272 B)
#define XSTR    272
#define SM_W    69632        // W bf16 [64 k][264 c] (stride 528 B)
#define WSTR    528
#define SM_AT   103424       // at bf16 [64 k][136 p] (stride 272 B)
#define ASTR    272
#define SM_LOG  120832       // logits f32 [128 p][66]
#define LSTR    66
#define SM_INV  154624       // 128 f
#define SM_SQ   155136       // 128 x 17 f (padded)
#define SM_RED  163840       // 1152 f
#define SM_ASUM 168448       // 64 f
#define SM_RK   168704       // 64 f
#define SM_BIAS 168960       // 64 f
#define SM_G2   169216       // 2 f
#define SM_TOTAL 169232

__device__ __forceinline__ uint32_t smem_u32(const void* p) {
    uint32_t a;
    asm("{ .reg .u64 t; cvta.to.shared.u64 t, %1; cvt.u32.u64 %0, t; }" : "=r"(a) : "l"(p));
    return a;
}
__device__ __forceinline__ uint32_t bf2(float lo, float hi) {
    uint32_t r;
    asm("cvt.rn.bf16x2.f32 %0, %1, %2;" : "=r"(r) : "f"(hi), "f"(lo));
    return r;
}
__device__ __forceinline__ void ldm4t(uint32_t* r, uint32_t addr) {
    asm volatile("ldmatrix.sync.aligned.m8n8.x4.trans.shared.b16 {%0,%1,%2,%3}, [%4];"
                 : "=r"(r[0]), "=r"(r[1]), "=r"(r[2]), "=r"(r[3]) : "r"(addr));
}
__device__ __forceinline__ void ldm4(uint32_t* r, uint32_t addr) {
    asm volatile("ldmatrix.sync.aligned.m8n8.x4.shared.b16 {%0,%1,%2,%3}, [%4];"
                 : "=r"(r[0]), "=r"(r[1]), "=r"(r[2]), "=r"(r[3]) : "r"(addr));
}
__device__ __forceinline__ void mma_bf16(float* d, const uint32_t* a, uint32_t b0, uint32_t b1) {
    asm volatile("mma.sync.aligned.m16n8k16.row.col.f32.bf16.bf16.f32 "
                 "{%0,%1,%2,%3}, {%4,%5,%6,%7}, {%8,%9}, {%0,%1,%2,%3};"
                 : "+f"(d[0]), "+f"(d[1]), "+f"(d[2]), "+f"(d[3])
                 : "r"(a[0]), "r"(a[1]), "r"(a[2]), "r"(a[3]), "r"(b0), "r"(b1));
}
__device__ __forceinline__ void pfL2(const void* p) {
    asm volatile("prefetch.global.L2 [%0];" :: "l"(p));
}

__global__ __launch_bounds__(512, 1) void netvlad_mma(
    const float* __restrict__ x, const float* __restrict__ w,
    const float* __restrict__ b, const float* __restrict__ cent,
    float* __restrict__ out) {
    extern __shared__ char smem[];
    float* smf = (float*)smem;
    const uint32_t sb = smem_u32(smem);
    const int t = threadIdx.x, lane = t & 31, wp = t >> 5;
    const int n = blockIdx.x;
    const float* xn = x + (size_t)n * CD * PT;

    // ---- one-time: W -> bf16 smem, bias, asum=0 ----
#pragma unroll
    for (int i = 0; i < 16; i++) {
        int id2 = t + (i << 9);                 // float2 index over 64x256
        int kk = id2 >> 7, c2 = id2 & 127;
        float2 v = ((const float2*)w)[id2];
        *(uint32_t*)(smem + SM_W + kk * WSTR + c2 * 4) = bf2(v.x, v.y);
    }
    if (t < KK) { smf[(SM_BIAS >> 2) + t] = b[t]; smf[(SM_ASUM >> 2) + t] = 0.f; }
    __syncthreads();

    float agg[4][2][4];
#pragma unroll
    for (int i = 0; i < 4; i++)
#pragma unroll
        for (int j = 0; j < 2; j++)
#pragma unroll
            for (int q = 0; q < 4; q++) agg[i][j][q] = 0.f;

    const int la = lane & 7, grp = lane >> 3;

    for (int tl = 0; tl < 8; tl++) {
        const int p0 = tl * 128;

        // ---- phase A: x -> bf16 smem + square partials ----
        {
            const int pq = t & 31, cb = t >> 5;       // cb 0..15
            const float* xp = xn + p0 + pq * 4;
            float s0 = 0.f, s1 = 0.f, s2 = 0.f, s3 = 0.f;
#pragma unroll
            for (int i = 0; i < 16; i++) {
                int c = cb + (i << 4);
                float4 v = *(const float4*)(xp + (size_t)c * PT);
                s0 += v.x * v.x; s1 += v.y * v.y; s2 += v.z * v.z; s3 += v.w * v.w;
                uint2 u = make_uint2(bf2(v.x, v.y), bf2(v.z, v.w));
                *(uint2*)(smem + SM_X + c * XSTR + pq * 8) = u;
            }
            float* sq = smf + (SM_SQ >> 2);
            sq[(pq * 4 + 0) * 17 + cb] = s0;
            sq[(pq * 4 + 1) * 17 + cb] = s1;
            sq[(pq * 4 + 2) * 17 + cb] = s2;
            sq[(pq * 4 + 3) * 17 + cb] = s3;
        }
        __syncthreads();

        // ---- inv (first 128 threads) + prefetch next tile + GEMM1 ----
        if (t < 128) {
            const float* sq = smf + (SM_SQ >> 2) + t * 17;
            float q = 0.f;
#pragma unroll
            for (int i = 0; i < 16; i++) q += sq[i];
            smf[(SM_INV >> 2) + t] = 1.0f / fmaxf(sqrtf(q), 1e-12f);
        }
        if (tl < 7) {
            const float* pf = xn + (size_t)(t >> 1) * PT + (p0 + 128) + ((t & 1) << 6);
            pfL2(pf); pfL2(pf + 32);
        }

        // ---- phase C: GEMM1 logits[p][k] = x^T W^T (16 warps: 8 mg x 2 ng) ----
        {
            const int mg = wp >> 1, ng = wp & 1;
            float acc[4][4];
#pragma unroll
            for (int i = 0; i < 4; i++)
#pragma unroll
                for (int q = 0; q < 4; q++) acc[i][q] = 0.f;
            const int pA = mg * 16 + ((grp & 1) << 3);
#pragma unroll
            for (int ks = 0; ks < 16; ks++) {
                const int cbase = ks * 16;
                uint32_t af[4];
                ldm4t(af, sb + SM_X + (cbase + la + ((grp >> 1) << 3)) * XSTR + pA * 2);
#pragma unroll
                for (int nt = 0; nt < 4; nt++) {
                    int kk = ng * 32 + nt * 8 + (lane >> 2);
                    const char* wr = smem + SM_W + kk * WSTR + (cbase + ((lane & 3) << 1)) * 2;
                    uint32_t b0 = *(const uint32_t*)wr;
                    uint32_t b1 = *(const uint32_t*)(wr + 16);
                    mma_bf16(acc[nt], af, b0, b1);
                }
            }
#pragma unroll
            for (int nt = 0; nt < 4; nt++) {
                int p = mg * 16 + (lane >> 2);
                int k = ng * 32 + nt * 8 + ((lane & 3) << 1);
                *(float2*)(smem + SM_LOG + (p * LSTR + k) * 4) = make_float2(acc[nt][0], acc[nt][1]);
                *(float2*)(smem + SM_LOG + ((p + 8) * LSTR + k) * 4) = make_float2(acc[nt][2], acc[nt][3]);
            }
        }
        __syncthreads();

        // ---- phase D: softmax (4 threads per pixel, 16 k each) ----
        {
            const int p = t >> 2, kh = t & 3;
            const float invp = smf[(SM_INV >> 2) + p];
            float lg[16];
            const float2* lp = (const float2*)(smem + SM_LOG + (p * LSTR + kh * 16) * 4);
#pragma unroll
            for (int j = 0; j < 8; j++) {
                float2 v = lp[j];
                lg[2 * j] = v.x; lg[2 * j + 1] = v.y;
            }
            float mx = -1e30f;
#pragma unroll
            for (int j = 0; j < 16; j++) {
                lg[j] = lg[j] * invp + smf[(SM_BIAS >> 2) + kh * 16 + j];
                mx = fmaxf(mx, lg[j]);
            }
            mx = fmaxf(mx, __shfl_xor_sync(0xffffffffu, mx, 1));
            mx = fmaxf(mx, __shfl_xor_sync(0xffffffffu, mx, 2));
            float sum = 0.f;
#pragma unroll
            for (int j = 0; j < 16; j++) { lg[j] = __expf(lg[j] - mx); sum += lg[j]; }
            sum += __shfl_xor_sync(0xffffffffu, sum, 1);
            sum += __shfl_xor_sync(0xffffffffu, sum, 2);
            const float rs = 1.0f / sum, rsv = rs * invp;
#pragma unroll
            for (int j = 0; j < 16; j++) {
                float a = lg[j] * rs;
                *(__nv_bfloat16*)(smem + SM_AT + (kh * 16 + j) * ASTR + p * 2) =
                    __float2bfloat16(lg[j] * rsv);
                float v = a;
                v += __shfl_xor_sync(0xffffffffu, v, 4);
                v += __shfl_xor_sync(0xffffffffu, v, 8);
                v += __shfl_xor_sync(0xffffffffu, v, 16);
                if (lane < 4) smf[(SM_RED >> 2) + wp * 64 + lane * 16 + j] = v;
            }
        }
        __syncthreads();

        // ---- asum fold (warps 0-1) + phase E: GEMM2 agg[k][c] += at @ x^T ----
        if (t < 64) {
            float s = 0.f;
#pragma unroll
            for (int i = 0; i < 16; i++) s += smf[(SM_RED >> 2) + i * 64 + t];
            smf[(SM_ASUM >> 2) + t] += s;
        }
        {
            const int cw = wp * 16;
#pragma unroll
            for (int ks = 0; ks < 8; ks++) {
                const int pb = ks * 16;
                uint32_t af[4][4];
#pragma unroll
                for (int mt = 0; mt < 4; mt++) {
                    int kR = mt * 16 + la + ((grp & 1) << 3);
                    int pA = pb + ((grp >> 1) << 3);
                    ldm4(af[mt], sb + SM_AT + kR * ASTR + pA * 2);
                }
#pragma unroll
                for (int nt = 0; nt < 2; nt++) {
                    int c = cw + nt * 8 + (lane >> 2);
                    const char* xr = smem + SM_X + c * XSTR + (pb + ((lane & 3) << 1)) * 2;
                    uint32_t b0 = *(const uint32_t*)xr;
                    uint32_t b1 = *(const uint32_t*)(xr + 16);
#pragma unroll
                    for (int mt = 0; mt < 4; mt++) mma_bf16(agg[mt][nt], af[mt], b0, b1);
                }
            }
        }
        __syncthreads();
    }

    // ---- epilogue: vlad = agg - asum*cent, intra-norm, global norm, store ----
#pragma unroll
    for (int mt = 0; mt < 4; mt++) {
        int k0 = mt * 16 + (lane >> 2);
        float as0 = smf[(SM_ASUM >> 2) + k0];
        float as1 = smf[(SM_ASUM >> 2) + k0 + 8];
#pragma unroll
        for (int nt = 0; nt < 2; nt++) {
            int c0 = wp * 16 + nt * 8 + ((lane & 3) << 1);
            float2 ce0 = *(const float2*)(cent + k0 * CD + c0);
            float2 ce1 = *(const float2*)(cent + (k0 + 8) * CD + c0);
            agg[mt][nt][0] -= as0 * ce0.x;
            agg[mt][nt][1] -= as0 * ce0.y;
            agg[mt][nt][2] -= as1 * ce1.x;
            agg[mt][nt][3] -= as1 * ce1.y;
        }
    }
#pragma unroll
    for (int mt = 0; mt < 4; mt++) {
        float sA = 0.f, sB = 0.f;
#pragma unroll
        for (int nt = 0; nt < 2; nt++) {
            sA += agg[mt][nt][0] * agg[mt][nt][0] + agg[mt][nt][1] * agg[mt][nt][1];
            sB += agg[mt][nt][2] * agg[mt][nt][2] + agg[mt][nt][3] * agg[mt][nt][3];
        }
        sA += __shfl_xor_sync(0xffffffffu, sA, 1);
        sA += __shfl_xor_sync(0xffffffffu, sA, 2);
        sB += __shfl_xor_sync(0xffffffffu, sB, 1);
        sB += __shfl_xor_sync(0xffffffffu, sB, 2);
        if ((lane & 3) == 0) {
            smf[(SM_RED >> 2) + (mt * 16 + (lane >> 2)) * 17 + wp] = sA;
            smf[(SM_RED >> 2) + (mt * 16 + 8 + (lane >> 2)) * 17 + wp] = sB;
        }
    }
    __syncthreads();
    if (t < 64) {
        float ss = 0.f;
#pragma unroll
        for (int i = 0; i < 16; i++) ss += smf[(SM_RED >> 2) + t * 17 + i];
        float dk = fmaxf(sqrtf(ss), 1e-12f);
        smf[(SM_RK >> 2) + t] = 1.0f / dk;
        float gp = ss / (dk * dk);
        gp += __shfl_xor_sync(0xffffffffu, gp, 16);
        gp += __shfl_xor_sync(0xffffffffu, gp, 8);
        gp += __shfl_xor_sync(0xffffffffu, gp, 4);
        gp += __shfl_xor_sync(0xffffffffu, gp, 2);
        gp += __shfl_xor_sync(0xffffffffu, gp, 1);
        if (lane == 0) smf[(SM_G2 >> 2) + wp] = gp;
    }
    __syncthreads();
    const float rg = 1.0f / fmaxf(sqrtf(smf[SM_G2 >> 2] + smf[(SM_G2 >> 2) + 1]), 1e-12f);
    float* on = out + (size_t)n * KK * CD;
#pragma unroll
    for (int mt = 0; mt < 4; mt++) {
        int k0 = mt * 16 + (lane >> 2);
        float r0 = smf[(SM_RK >> 2) + k0] * rg;
        float r1 = smf[(SM_RK >> 2) + k0 + 8] * rg;
#pragma unroll
        for (int nt = 0; nt < 2; nt++) {
            int c0 = wp * 16 + nt * 8 + ((lane & 3) << 1);
            *(float2*)(on + k0 * CD + c0) =
                make_float2(agg[mt][nt][0] * r0, agg[mt][nt][1] * r0);
            *(float2*)(on + (k0 + 8) * CD + c0) =
                make_float2(agg[mt][nt][2] * r1, agg[mt][nt][3] * r1);
        }
    }
}

// ------------------------------------------------------------------------------
extern "C" void kernel_launch(void* const* d_in, const int* in_sizes, int n_in,
                              void* d_out, int out_size) {
    const float* x    = (const float*)d_in[0];  // (128, 256, 32, 32)
    const float* w    = (const float*)d_in[1];  // (64, 256)
    const float* b    = (const float*)d_in[2];  // (64)
    const float* cent = (const float*)d_in[3];  // (64, 256)
    float* out = (float*)d_out;                 // (128, 16384)

    cudaFuncSetAttribute(netvlad_mma, cudaFuncAttributeMaxDynamicSharedMemorySize, SM_TOTAL);
    netvlad_mma<<<NB, 512, SM_TOTAL>>>(x, w, b, cent, out);
}

// round 6
// speedup vs baseline: 5.9598x; 1.1134x over previous
#include <cuda_runtime.h>
#include <cuda_bf16.h>
#include <cstdint>

#define NB 128
#define CD 256
#define KK 64
#define PT 1024

// ---- smem byte offsets ----
#define SM_X    0            // x tile bf16 [256 c][136 p] (stride 272 B)
#define XSTR    272
#define SM_W    69632        // W bf16 [64 k][264 c] (stride 528 B)
#define WSTR    528
#define SM_AT   103424       // at bf16 [64 k][136 p] (stride 272 B)
#define ASTR    272
#define SM_EX   120832       // softmax exchange [128 p][4 f] (m0,s0,m1,s1)
#define SM_SQ   122880       // 128 x 17 f
#define SM_RED  131584       // 64 x 17 f (asum partials use [64][8])
#define SM_ASUM 135936       // 64 f
#define SM_RK   136192       // 64 f
#define SM_G2   136448       // 2 f
#define SM_TOTAL 136464

__device__ __forceinline__ uint32_t smem_u32(const void* p) {
    uint32_t a;
    asm("{ .reg .u64 t; cvta.to.shared.u64 t, %1; cvt.u32.u64 %0, t; }" : "=r"(a) : "l"(p));
    return a;
}
__device__ __forceinline__ uint32_t bf2(float lo, float hi) {
    uint32_t r;
    asm("cvt.rn.bf16x2.f32 %0, %1, %2;" : "=r"(r) : "f"(hi), "f"(lo));
    return r;
}
__device__ __forceinline__ void ldm4t(uint32_t* r, uint32_t addr) {
    asm volatile("ldmatrix.sync.aligned.m8n8.x4.trans.shared.b16 {%0,%1,%2,%3}, [%4];"
                 : "=r"(r[0]), "=r"(r[1]), "=r"(r[2]), "=r"(r[3]) : "r"(addr));
}
__device__ __forceinline__ void ldm4(uint32_t* r, uint32_t addr) {
    asm volatile("ldmatrix.sync.aligned.m8n8.x4.shared.b16 {%0,%1,%2,%3}, [%4];"
                 : "=r"(r[0]), "=r"(r[1]), "=r"(r[2]), "=r"(r[3]) : "r"(addr));
}
__device__ __forceinline__ void mma_bf16(float* d, const uint32_t* a, uint32_t b0, uint32_t b1) {
    asm volatile("mma.sync.aligned.m16n8k16.row.col.f32.bf16.bf16.f32 "
                 "{%0,%1,%2,%3}, {%4,%5,%6,%7}, {%8,%9}, {%0,%1,%2,%3};"
                 : "+f"(d[0]), "+f"(d[1]), "+f"(d[2]), "+f"(d[3])
                 : "r"(a[0]), "r"(a[1]), "r"(a[2]), "r"(a[3]), "r"(b0), "r"(b1));
}
__device__ __forceinline__ void pfL2(const void* p) {
    asm volatile("prefetch.global.L2 [%0];" :: "l"(p));
}

__global__ __launch_bounds__(512, 1) void netvlad_mma(
    const float* __restrict__ x, const float* __restrict__ w,
    const float* __restrict__ b, const float* __restrict__ cent,
    float* __restrict__ out) {
    extern __shared__ char smem[];
    float* smf = (float*)smem;
    const uint32_t sb = smem_u32(smem);
    const int t = threadIdx.x, lane = t & 31, wp = t >> 5;
    const int la = lane & 7, grp = lane >> 3, qr = lane >> 2, qc = lane & 3;
    const int mg = wp >> 1, ng = wp & 1;
    const int n = blockIdx.x;
    const float* xn = x + (size_t)n * CD * PT;

    // ---- one-time: W -> bf16 smem, asum=0, per-lane bias regs ----
#pragma unroll
    for (int i = 0; i < 16; i++) {
        int id2 = t + (i << 9);
        int kk = id2 >> 7, c2 = id2 & 127;
        float2 v = ((const float2*)w)[id2];
        *(uint32_t*)(smem + SM_W + kk * WSTR + c2 * 4) = bf2(v.x, v.y);
    }
    if (t < KK) smf[(SM_ASUM >> 2) + t] = 0.f;
    float bsv[8];
#pragma unroll
    for (int nt = 0; nt < 4; nt++) {
        bsv[nt * 2]     = b[ng * 32 + nt * 8 + qc * 2];
        bsv[nt * 2 + 1] = b[ng * 32 + nt * 8 + qc * 2 + 1];
    }

    // precomputed ldmatrix base addresses
    const uint32_t aG1 = sb + SM_X + (uint32_t)(la + ((grp >> 1) << 3)) * XSTR +
                         (uint32_t)(mg * 16 + ((grp & 1) << 3)) * 2;
    const uint32_t wG1 = sb + SM_W + (uint32_t)(ng * 32 + la) * WSTR + (uint32_t)(grp * 8) * 2;
    const uint32_t aG2 = sb + SM_AT + (uint32_t)(la + ((grp & 1) << 3)) * ASTR +
                         (uint32_t)((grp >> 1) << 3) * 2;
    const uint32_t xG2_0 = sb + SM_X + (uint32_t)(wp * 16 + la) * XSTR + (uint32_t)(grp * 8) * 2;
    const uint32_t xG2_1 = xG2_0 + 8 * XSTR;

    const int plo = mg * 16 + qr, phi = plo + 8;

    float agg[4][2][4];
#pragma unroll
    for (int i = 0; i < 4; i++)
#pragma unroll
        for (int j = 0; j < 2; j++)
#pragma unroll
            for (int q = 0; q < 4; q++) agg[i][j][q] = 0.f;

    __syncthreads();

    for (int tl = 0; tl < 8; tl++) {
        const int p0 = tl * 128;

        // ---- phase A: x -> bf16 smem + square partials ----
        {
            const int pq = t & 31, cb = t >> 5;
            const float* xp = xn + p0 + pq * 4;
            float s0 = 0.f, s1 = 0.f, s2 = 0.f, s3 = 0.f;
#pragma unroll
            for (int i = 0; i < 16; i++) {
                int c = cb + (i << 4);
                float4 v = *(const float4*)(xp + (size_t)c * PT);
                s0 += v.x * v.x; s1 += v.y * v.y; s2 += v.z * v.z; s3 += v.w * v.w;
                uint2 u = make_uint2(bf2(v.x, v.y), bf2(v.z, v.w));
                *(uint2*)(smem + SM_X + c * XSTR + pq * 8) = u;
            }
            float* sq = smf + (SM_SQ >> 2);
            sq[(pq * 4 + 0) * 17 + cb] = s0;
            sq[(pq * 4 + 1) * 17 + cb] = s1;
            sq[(pq * 4 + 2) * 17 + cb] = s2;
            sq[(pq * 4 + 3) * 17 + cb] = s3;
        }
        __syncthreads();

        if (tl < 7) {
            const float* pf = xn + (size_t)(t >> 1) * PT + (p0 + 128) + ((t & 1) << 6);
            pfL2(pf); pfL2(pf + 32);
        }

        // ---- GEMM1: logits[p][k] = x^T W^T, logits stay in registers ----
        float acc[4][4];
#pragma unroll
        for (int i = 0; i < 4; i++)
#pragma unroll
            for (int q = 0; q < 4; q++) acc[i][q] = 0.f;
#pragma unroll
        for (int cb32 = 0; cb32 < 256; cb32 += 32) {
            uint32_t afA[4], afB[4];
            ldm4t(afA, aG1 + (uint32_t)cb32 * XSTR);
            ldm4t(afB, aG1 + (uint32_t)(cb32 + 16) * XSTR);
#pragma unroll
            for (int nt = 0; nt < 4; nt++) {
                uint32_t wf[4];
                ldm4(wf, wG1 + (uint32_t)nt * (8 * WSTR) + (uint32_t)cb32 * 2);
                mma_bf16(acc[nt], afA, wf[0], wf[1]);
                mma_bf16(acc[nt], afB, wf[2], wf[3]);
            }
        }

        // ---- fused softmax part 1: in-warp inv, scale+bias, local max/sum, exchange ----
        float qlo = 0.f, qhi = 0.f;
#pragma unroll
        for (int i = 0; i < 4; i++) {
            qlo += smf[(SM_SQ >> 2) + plo * 17 + qc * 4 + i];
            qhi += smf[(SM_SQ >> 2) + phi * 17 + qc * 4 + i];
        }
        qlo += __shfl_xor_sync(0xffffffffu, qlo, 1);
        qlo += __shfl_xor_sync(0xffffffffu, qlo, 2);
        qhi += __shfl_xor_sync(0xffffffffu, qhi, 1);
        qhi += __shfl_xor_sync(0xffffffffu, qhi, 2);
        const float invlo = 1.0f / fmaxf(sqrtf(qlo), 1e-12f);
        const float invhi = 1.0f / fmaxf(sqrtf(qhi), 1e-12f);

        float mlo = -1e30f, mhi = -1e30f;
#pragma unroll
        for (int nt = 0; nt < 4; nt++) {
            acc[nt][0] = acc[nt][0] * invlo + bsv[nt * 2];
            acc[nt][1] = acc[nt][1] * invlo + bsv[nt * 2 + 1];
            acc[nt][2] = acc[nt][2] * invhi + bsv[nt * 2];
            acc[nt][3] = acc[nt][3] * invhi + bsv[nt * 2 + 1];
            mlo = fmaxf(mlo, fmaxf(acc[nt][0], acc[nt][1]));
            mhi = fmaxf(mhi, fmaxf(acc[nt][2], acc[nt][3]));
        }
        mlo = fmaxf(mlo, __shfl_xor_sync(0xffffffffu, mlo, 1));
        mlo = fmaxf(mlo, __shfl_xor_sync(0xffffffffu, mlo, 2));
        mhi = fmaxf(mhi, __shfl_xor_sync(0xffffffffu, mhi, 1));
        mhi = fmaxf(mhi, __shfl_xor_sync(0xffffffffu, mhi, 2));
        float slo = 0.f, shi = 0.f;
#pragma unroll
        for (int nt = 0; nt < 4; nt++) {
            acc[nt][0] = __expf(acc[nt][0] - mlo); slo += acc[nt][0];
            acc[nt][1] = __expf(acc[nt][1] - mlo); slo += acc[nt][1];
            acc[nt][2] = __expf(acc[nt][2] - mhi); shi += acc[nt][2];
            acc[nt][3] = __expf(acc[nt][3] - mhi); shi += acc[nt][3];
        }
        slo += __shfl_xor_sync(0xffffffffu, slo, 1);
        slo += __shfl_xor_sync(0xffffffffu, slo, 2);
        shi += __shfl_xor_sync(0xffffffffu, shi, 1);
        shi += __shfl_xor_sync(0xffffffffu, shi, 2);
        if (qc == 0) {
            *(float2*)(smem + SM_EX + plo * 16 + ng * 8) = make_float2(mlo, slo);
            *(float2*)(smem + SM_EX + phi * 16 + ng * 8) = make_float2(mhi, shi);
        }
        __syncthreads();

        // ---- fused softmax part 2: merge across ng, write at (bf16), asum partials ----
        {
            float4 exl = *(float4*)(smem + SM_EX + plo * 16);
            float4 exh = *(float4*)(smem + SM_EX + phi * 16);
            float Ml = fmaxf(exl.x, exl.z), Mh = fmaxf(exh.x, exh.z);
            float Sl = exl.y * __expf(exl.x - Ml) + exl.w * __expf(exl.z - Ml);
            float Sh = exh.y * __expf(exh.x - Mh) + exh.w * __expf(exh.z - Mh);
            float scl = __expf(mlo - Ml) / Sl;
            float sch = __expf(mhi - Mh) / Sh;
            float asv[8];
            const int kb = ng * 32 + qc * 2;
#pragma unroll
            for (int nt = 0; nt < 4; nt++) {
                float a0 = acc[nt][0] * scl, a1 = acc[nt][1] * scl;
                float a2 = acc[nt][2] * sch, a3 = acc[nt][3] * sch;
                asv[nt * 2]     = a0 + a2;
                asv[nt * 2 + 1] = a1 + a3;
                float t0 = a0 * invlo, t1 = a1 * invlo;
                float t2 = a2 * invhi, t3 = a3 * invhi;
                float u0 = __shfl_xor_sync(0xffffffffu, t0, 4);
                float u1 = __shfl_xor_sync(0xffffffffu, t1, 4);
                float u2 = __shfl_xor_sync(0xffffffffu, t2, 4);
                float u3 = __shfl_xor_sync(0xffffffffu, t3, 4);
                if ((qr & 1) == 0) {
                    int k0 = kb + nt * 8;
                    *(uint32_t*)(smem + SM_AT + k0 * ASTR + plo * 2) = bf2(t0, u0);
                    *(uint32_t*)(smem + SM_AT + (k0 + 1) * ASTR + plo * 2) = bf2(t1, u1);
                    *(uint32_t*)(smem + SM_AT + k0 * ASTR + phi * 2) = bf2(t2, u2);
                    *(uint32_t*)(smem + SM_AT + (k0 + 1) * ASTR + phi * 2) = bf2(t3, u3);
                }
            }
#pragma unroll
            for (int j = 0; j < 8; j++) {
                asv[j] += __shfl_xor_sync(0xffffffffu, asv[j], 4);
                asv[j] += __shfl_xor_sync(0xffffffffu, asv[j], 8);
                asv[j] += __shfl_xor_sync(0xffffffffu, asv[j], 16);
            }
            if (lane < 4) {
#pragma unroll
                for (int nt = 0; nt < 4; nt++) {
                    int k0 = ng * 32 + nt * 8 + lane * 2;
                    smf[(SM_RED >> 2) + k0 * 8 + mg] = asv[nt * 2];
                    smf[(SM_RED >> 2) + (k0 + 1) * 8 + mg] = asv[nt * 2 + 1];
                }
            }
        }
        __syncthreads();

        // ---- asum fold + GEMM2: agg[k][c] += at @ x^T ----
        if (t < 64) {
            float s = 0.f;
#pragma unroll
            for (int i = 0; i < 8; i++) s += smf[(SM_RED >> 2) + t * 8 + i];
            smf[(SM_ASUM >> 2) + t] += s;
        }
#pragma unroll
        for (int ks2 = 0; ks2 < 4; ks2++) {
            const uint32_t pb2 = (uint32_t)(ks2 * 32) * 2;
            uint32_t bf0[4], bf1[4];
            ldm4(bf0, xG2_0 + pb2);
            ldm4(bf1, xG2_1 + pb2);
#pragma unroll
            for (int mt = 0; mt < 4; mt++) {
                uint32_t af0[4], af1[4];
                ldm4(af0, aG2 + (uint32_t)mt * 16 * ASTR + pb2);
                ldm4(af1, aG2 + (uint32_t)mt * 16 * ASTR + pb2 + 32);
                mma_bf16(agg[mt][0], af0, bf0[0], bf0[1]);
                mma_bf16(agg[mt][1], af0, bf1[0], bf1[1]);
                mma_bf16(agg[mt][0], af1, bf0[2], bf0[3]);
                mma_bf16(agg[mt][1], af1, bf1[2], bf1[3]);
            }
        }
        __syncthreads();
    }

    // ---- epilogue: vlad = agg - asum*cent, intra-norm, global norm, store ----
#pragma unroll
    for (int mt = 0; mt < 4; mt++) {
        int k0 = mt * 16 + qr;
        float as0 = smf[(SM_ASUM >> 2) + k0];
        float as1 = smf[(SM_ASUM >> 2) + k0 + 8];
#pragma unroll
        for (int nt = 0; nt < 2; nt++) {
            int c0 = wp * 16 + nt * 8 + qc * 2;
            float2 ce0 = *(const float2*)(cent + k0 * CD + c0);
            float2 ce1 = *(const float2*)(cent + (k0 + 8) * CD + c0);
            agg[mt][nt][0] -= as0 * ce0.x;
            agg[mt][nt][1] -= as0 * ce0.y;
            agg[mt][nt][2] -= as1 * ce1.x;
            agg[mt][nt][3] -= as1 * ce1.y;
        }
    }
#pragma unroll
    for (int mt = 0; mt < 4; mt++) {
        float sA = 0.f, sB = 0.f;
#pragma unroll
        for (int nt = 0; nt < 2; nt++) {
            sA += agg[mt][nt][0] * agg[mt][nt][0] + agg[mt][nt][1] * agg[mt][nt][1];
            sB += agg[mt][nt][2] * agg[mt][nt][2] + agg[mt][nt][3] * agg[mt][nt][3];
        }
        sA += __shfl_xor_sync(0xffffffffu, sA, 1);
        sA += __shfl_xor_sync(0xffffffffu, sA, 2);
        sB += __shfl_xor_sync(0xffffffffu, sB, 1);
        sB += __shfl_xor_sync(0xffffffffu, sB, 2);
        if (qc == 0) {
            smf[(SM_RED >> 2) + (mt * 16 + qr) * 17 + wp] = sA;
            smf[(SM_RED >> 2) + (mt * 16 + 8 + qr) * 17 + wp] = sB;
        }
    }
    __syncthreads();
    if (t < 64) {
        float ss = 0.f;
#pragma unroll
        for (int i = 0; i < 16; i++) ss += smf[(SM_RED >> 2) + t * 17 + i];
        float dk = fmaxf(sqrtf(ss), 1e-12f);
        smf[(SM_RK >> 2) + t] = 1.0f / dk;
        float gp = ss / (dk * dk);
        gp += __shfl_xor_sync(0xffffffffu, gp, 16);
        gp += __shfl_xor_sync(0xffffffffu, gp, 8);
        gp += __shfl_xor_sync(0xffffffffu, gp, 4);
        gp += __shfl_xor_sync(0xffffffffu, gp, 2);
        gp += __shfl_xor_sync(0xffffffffu, gp, 1);
        if (lane == 0) smf[(SM_G2 >> 2) + wp] = gp;
    }
    __syncthreads();
    const float rg = 1.0f / fmaxf(sqrtf(smf[SM_G2 >> 2] + smf[(SM_G2 >> 2) + 1]), 1e-12f);
    float* on = out + (size_t)n * KK * CD;
#pragma unroll
    for (int mt = 0; mt < 4; mt++) {
        int k0 = mt * 16 + qr;
        float r0 = smf[(SM_RK >> 2) + k0] * rg;
        float r1 = smf[(SM_RK >> 2) + k0 + 8] * rg;
#pragma unroll
        for (int nt = 0; nt < 2; nt++) {
            int c0 = wp * 16 + nt * 8 + qc * 2;
            *(float2*)(on + k0 * CD + c0) =
                make_float2(agg[mt][nt][0] * r0, agg[mt][nt][1] * r0);
            *(float2*)(on + (k0 + 8) * CD + c0) =
                make_float2(agg[mt][nt][2] * r1, agg[mt][nt][3] * r1);
        }
    }
}

// ------------------------------------------------------------------------------
extern "C" void kernel_launch(void* const* d_in, const int* in_sizes, int n_in,
                              void* d_out, int out_size) {
    const float* x    = (const float*)d_in[0];  // (128, 256, 32, 32)
    const float* w    = (const float*)d_in[1];  // (64, 256)
    const float* b    = (const float*)d_in[2];  // (64)
    const float* cent = (const float*)d_in[3];  // (64, 256)
    float* out = (float*)d_out;                 // (128, 16384)

    cudaFuncSetAttribute(netvlad_mma, cudaFuncAttributeMaxDynamicSharedMemorySize, SM_TOTAL);
    netvlad_mma<<<NB, 512, SM_TOTAL>>>(x, w, b, cent, out);
}

// round 7
// speedup vs baseline: 6.5124x; 1.0927x over previous
#include <cuda_runtime.h>
#include <cuda_bf16.h>
#include <cstdint>

#define NB 128
#define CD 256
#define KK 64
#define PT 1024

// ---- smem byte offsets ----
#define SM_X0   0            // x tile bf16 [256 c][136 p] (stride 272 B), buffer 0
#define SM_X1   69632        // buffer 1
#define XSTR    272
#define SM_W    139264       // W bf16 [64 k][264 c] (stride 528 B)
#define WSTR    528
#define SM_AT   173056       // at bf16 [64 k][136 p] (stride 272 B)
#define ASTR    272
#define SM_EX   190464       // softmax exchange [128 p][4 f]
#define SM_SQ   192512       // 128 x 17 f
#define SM_RED  201216       // 64 x 17 f
#define SM_ASUM 205568       // 64 f
#define SM_RK   205824       // 64 f
#define SM_G2   206080       // 2 f
#define SM_TOTAL 206088

__device__ __forceinline__ uint32_t smem_u32(const void* p) {
    uint32_t a;
    asm("{ .reg .u64 t; cvta.to.shared.u64 t, %1; cvt.u32.u64 %0, t; }" : "=r"(a) : "l"(p));
    return a;
}
__device__ __forceinline__ uint32_t bf2(float lo, float hi) {
    uint32_t r;
    asm("cvt.rn.bf16x2.f32 %0, %1, %2;" : "=r"(r) : "f"(hi), "f"(lo));
    return r;
}
__device__ __forceinline__ void ldm4t(uint32_t* r, uint32_t addr) {
    asm volatile("ldmatrix.sync.aligned.m8n8.x4.trans.shared.b16 {%0,%1,%2,%3}, [%4];"
                 : "=r"(r[0]), "=r"(r[1]), "=r"(r[2]), "=r"(r[3]) : "r"(addr));
}
__device__ __forceinline__ void ldm4(uint32_t* r, uint32_t addr) {
    asm volatile("ldmatrix.sync.aligned.m8n8.x4.shared.b16 {%0,%1,%2,%3}, [%4];"
                 : "=r"(r[0]), "=r"(r[1]), "=r"(r[2]), "=r"(r[3]) : "r"(addr));
}
__device__ __forceinline__ void mma_bf16(float* d, const uint32_t* a, uint32_t b0, uint32_t b1) {
    asm volatile("mma.sync.aligned.m16n8k16.row.col.f32.bf16.bf16.f32 "
                 "{%0,%1,%2,%3}, {%4,%5,%6,%7}, {%8,%9}, {%0,%1,%2,%3};"
                 : "+f"(d[0]), "+f"(d[1]), "+f"(d[2]), "+f"(d[3])
                 : "r"(a[0]), "r"(a[1]), "r"(a[2]), "r"(a[3]), "r"(b0), "r"(b1));
}
__device__ __forceinline__ void pfL2(const void* p) {
    asm volatile("prefetch.global.L2 [%0];" :: "l"(p));
}

__global__ __launch_bounds__(512, 1) void netvlad_mma(
    const float* __restrict__ x, const float* __restrict__ w,
    const float* __restrict__ b, const float* __restrict__ cent,
    float* __restrict__ out) {
    extern __shared__ char smem[];
    float* smf = (float*)smem;
    const uint32_t sb = smem_u32(smem);
    const int t = threadIdx.x, lane = t & 31, wp = t >> 5;
    const int la = lane & 7, grp = lane >> 3, qr = lane >> 2, qc = lane & 3;
    const int mg = wp >> 1, ng = wp & 1;
    const int n = blockIdx.x;
    const float* xn = x + (size_t)n * CD * PT;

    // ---- one-time: W -> bf16 smem, asum=0, per-lane bias regs ----
#pragma unroll
    for (int i = 0; i < 16; i++) {
        int id2 = t + (i << 9);
        int kk = id2 >> 7, c2 = id2 & 127;
        float2 v = ((const float2*)w)[id2];
        *(uint32_t*)(smem + SM_W + kk * WSTR + c2 * 4) = bf2(v.x, v.y);
    }
    if (t < KK) smf[(SM_ASUM >> 2) + t] = 0.f;
    float bsv[8];
#pragma unroll
    for (int nt = 0; nt < 4; nt++) {
        bsv[nt * 2]     = b[ng * 32 + nt * 8 + qc * 2];
        bsv[nt * 2 + 1] = b[ng * 32 + nt * 8 + qc * 2 + 1];
    }

    // ldmatrix offsets (buffer-relative for X)
    const uint32_t aG1off = (uint32_t)(la + ((grp >> 1) << 3)) * XSTR +
                            (uint32_t)(mg * 16 + ((grp & 1) << 3)) * 2;
    const uint32_t wG1 = sb + SM_W + (uint32_t)(ng * 32 + la) * WSTR + (uint32_t)(grp * 8) * 2;
    const uint32_t aG2 = sb + SM_AT + (uint32_t)(la + ((grp & 1) << 3)) * ASTR +
                         (uint32_t)((grp >> 1) << 3) * 2;
    const uint32_t xG2off0 = (uint32_t)(wp * 16 + la) * XSTR + (uint32_t)(grp * 8) * 2;
    const uint32_t xG2off1 = xG2off0 + 8 * XSTR;

    const int plo = mg * 16 + qr, phi = plo + 8;
    const int pq = t & 31, cb = t >> 5;

    float agg[4][2][4];
#pragma unroll
    for (int i = 0; i < 4; i++)
#pragma unroll
        for (int j = 0; j < 2; j++)
#pragma unroll
            for (int q = 0; q < 4; q++) agg[i][j][q] = 0.f;

    // ---- pre-loop: phase A for tile 0 into X0 ----
    {
        const float* xp = xn + pq * 4;
        float s0 = 0.f, s1 = 0.f, s2 = 0.f, s3 = 0.f;
#pragma unroll
        for (int i = 0; i < 16; i++) {
            int c = cb + (i << 4);
            float4 v = *(const float4*)(xp + (size_t)c * PT);
            s0 += v.x * v.x; s1 += v.y * v.y; s2 += v.z * v.z; s3 += v.w * v.w;
            *(uint2*)(smem + SM_X0 + c * XSTR + pq * 8) =
                make_uint2(bf2(v.x, v.y), bf2(v.z, v.w));
        }
        float* sq = smf + (SM_SQ >> 2);
        sq[(pq * 4 + 0) * 17 + cb] = s0;
        sq[(pq * 4 + 1) * 17 + cb] = s1;
        sq[(pq * 4 + 2) * 17 + cb] = s2;
        sq[(pq * 4 + 3) * 17 + cb] = s3;
    }
    __syncthreads();

    for (int tl = 0; tl < 8; tl++) {
        const uint32_t xb  = (tl & 1) ? SM_X1 : SM_X0;
        const uint32_t xnb = (tl & 1) ? SM_X0 : SM_X1;
        const uint32_t aG1 = sb + xb + aG1off;

        // L2-prefetch next tile (consumed by LDGs in the GEMM2 phase below)
        if (tl < 7) {
            const float* pf = xn + (size_t)(t >> 1) * PT + (tl * 128 + 128) + ((t & 1) << 6);
            pfL2(pf); pfL2(pf + 32);
        }

        // ---- GEMM1: logits[p][k], in registers ----
        float acc[4][4];
#pragma unroll
        for (int i = 0; i < 4; i++)
#pragma unroll
            for (int q = 0; q < 4; q++) acc[i][q] = 0.f;
#pragma unroll
        for (int cb32 = 0; cb32 < 256; cb32 += 32) {
            uint32_t afA[4], afB[4];
            ldm4t(afA, aG1 + (uint32_t)cb32 * XSTR);
            ldm4t(afB, aG1 + (uint32_t)(cb32 + 16) * XSTR);
#pragma unroll
            for (int nt = 0; nt < 4; nt++) {
                uint32_t wf[4];
                ldm4(wf, wG1 + (uint32_t)nt * (8 * WSTR) + (uint32_t)cb32 * 2);
                mma_bf16(acc[nt], afA, wf[0], wf[1]);
                mma_bf16(acc[nt], afB, wf[2], wf[3]);
            }
        }

        // ---- softmax part 1: inv from SQ, scale+bias, local max/sum, exchange ----
        float qlo = 0.f, qhi = 0.f;
#pragma unroll
        for (int i = 0; i < 4; i++) {
            qlo += smf[(SM_SQ >> 2) + plo * 17 + qc * 4 + i];
            qhi += smf[(SM_SQ >> 2) + phi * 17 + qc * 4 + i];
        }
        qlo += __shfl_xor_sync(0xffffffffu, qlo, 1);
        qlo += __shfl_xor_sync(0xffffffffu, qlo, 2);
        qhi += __shfl_xor_sync(0xffffffffu, qhi, 1);
        qhi += __shfl_xor_sync(0xffffffffu, qhi, 2);
        const float invlo = 1.0f / fmaxf(sqrtf(qlo), 1e-12f);
        const float invhi = 1.0f / fmaxf(sqrtf(qhi), 1e-12f);

        float mlo = -1e30f, mhi = -1e30f;
#pragma unroll
        for (int nt = 0; nt < 4; nt++) {
            acc[nt][0] = acc[nt][0] * invlo + bsv[nt * 2];
            acc[nt][1] = acc[nt][1] * invlo + bsv[nt * 2 + 1];
            acc[nt][2] = acc[nt][2] * invhi + bsv[nt * 2];
            acc[nt][3] = acc[nt][3] * invhi + bsv[nt * 2 + 1];
            mlo = fmaxf(mlo, fmaxf(acc[nt][0], acc[nt][1]));
            mhi = fmaxf(mhi, fmaxf(acc[nt][2], acc[nt][3]));
        }
        mlo = fmaxf(mlo, __shfl_xor_sync(0xffffffffu, mlo, 1));
        mlo = fmaxf(mlo, __shfl_xor_sync(0xffffffffu, mlo, 2));
        mhi = fmaxf(mhi, __shfl_xor_sync(0xffffffffu, mhi, 1));
        mhi = fmaxf(mhi, __shfl_xor_sync(0xffffffffu, mhi, 2));
        float slo = 0.f, shi = 0.f;
#pragma unroll
        for (int nt = 0; nt < 4; nt++) {
            acc[nt][0] = __expf(acc[nt][0] - mlo); slo += acc[nt][0];
            acc[nt][1] = __expf(acc[nt][1] - mlo); slo += acc[nt][1];
            acc[nt][2] = __expf(acc[nt][2] - mhi); shi += acc[nt][2];
            acc[nt][3] = __expf(acc[nt][3] - mhi); shi += acc[nt][3];
        }
        slo += __shfl_xor_sync(0xffffffffu, slo, 1);
        slo += __shfl_xor_sync(0xffffffffu, slo, 2);
        shi += __shfl_xor_sync(0xffffffffu, shi, 1);
        shi += __shfl_xor_sync(0xffffffffu, shi, 2);
        if (qc == 0) {
            *(float2*)(smem + SM_EX + plo * 16 + ng * 8) = make_float2(mlo, slo);
            *(float2*)(smem + SM_EX + phi * 16 + ng * 8) = make_float2(mhi, shi);
        }
        __syncthreads();   // S1

        // ---- softmax part 2: merge, write at (bf16), asum partials ----
        {
            float4 exl = *(float4*)(smem + SM_EX + plo * 16);
            float4 exh = *(float4*)(smem + SM_EX + phi * 16);
            float Ml = fmaxf(exl.x, exl.z), Mh = fmaxf(exh.x, exh.z);
            float Sl = exl.y * __expf(exl.x - Ml) + exl.w * __expf(exl.z - Ml);
            float Sh = exh.y * __expf(exh.x - Mh) + exh.w * __expf(exh.z - Mh);
            float scl = __expf(mlo - Ml) / Sl;
            float sch = __expf(mhi - Mh) / Sh;
            float asv[8];
            const int kb = ng * 32 + qc * 2;
#pragma unroll
            for (int nt = 0; nt < 4; nt++) {
                float a0 = acc[nt][0] * scl, a1 = acc[nt][1] * scl;
                float a2 = acc[nt][2] * sch, a3 = acc[nt][3] * sch;
                asv[nt * 2]     = a0 + a2;
                asv[nt * 2 + 1] = a1 + a3;
                float t0 = a0 * invlo, t1 = a1 * invlo;
                float t2 = a2 * invhi, t3 = a3 * invhi;
                float u0 = __shfl_xor_sync(0xffffffffu, t0, 4);
                float u1 = __shfl_xor_sync(0xffffffffu, t1, 4);
                float u2 = __shfl_xor_sync(0xffffffffu, t2, 4);
                float u3 = __shfl_xor_sync(0xffffffffu, t3, 4);
                if ((qr & 1) == 0) {
                    int k0 = kb + nt * 8;
                    *(uint32_t*)(smem + SM_AT + k0 * ASTR + plo * 2) = bf2(t0, u0);
                    *(uint32_t*)(smem + SM_AT + (k0 + 1) * ASTR + plo * 2) = bf2(t1, u1);
                    *(uint32_t*)(smem + SM_AT + k0 * ASTR + phi * 2) = bf2(t2, u2);
                    *(uint32_t*)(smem + SM_AT + (k0 + 1) * ASTR + phi * 2) = bf2(t3, u3);
                }
            }
#pragma unroll
            for (int j = 0; j < 8; j++) {
                asv[j] += __shfl_xor_sync(0xffffffffu, asv[j], 4);
                asv[j] += __shfl_xor_sync(0xffffffffu, asv[j], 8);
                asv[j] += __shfl_xor_sync(0xffffffffu, asv[j], 16);
            }
            if (lane < 4) {
#pragma unroll
                for (int nt = 0; nt < 4; nt++) {
                    int k0 = ng * 32 + nt * 8 + lane * 2;
                    smf[(SM_RED >> 2) + k0 * 8 + mg] = asv[nt * 2];
                    smf[(SM_RED >> 2) + (k0 + 1) * 8 + mg] = asv[nt * 2 + 1];
                }
            }
        }
        __syncthreads();   // S2

        // ---- asum fold + GEMM2 interleaved with phase A(tl+1) into other buffer ----
        if (t < 64) {
            float s = 0.f;
#pragma unroll
            for (int i = 0; i < 8; i++) s += smf[(SM_RED >> 2) + t * 8 + i];
            smf[(SM_ASUM >> 2) + t] += s;
        }
        {
            const uint32_t xg0 = sb + xb + xG2off0;
            const uint32_t xg1 = sb + xb + xG2off1;
            const float* xp = xn + (tl * 128 + 128) + pq * 4;   // next tile (tl<7)
            float s0 = 0.f, s1 = 0.f, s2 = 0.f, s3 = 0.f;
#pragma unroll
            for (int q4 = 0; q4 < 4; q4++) {
                float4 stg[4];
                if (tl < 7) {
#pragma unroll
                    for (int j = 0; j < 4; j++)
                        stg[j] = *(const float4*)(xp + (size_t)(cb + ((q4 * 4 + j) << 4)) * PT);
                }
                const uint32_t pb2 = (uint32_t)(q4 * 32) * 2;
                uint32_t bf0[4], bf1[4];
                ldm4(bf0, xg0 + pb2);
                ldm4(bf1, xg1 + pb2);
#pragma unroll
                for (int mt = 0; mt < 4; mt++) {
                    uint32_t af0[4], af1[4];
                    ldm4(af0, aG2 + (uint32_t)mt * 16 * ASTR + pb2);
                    ldm4(af1, aG2 + (uint32_t)mt * 16 * ASTR + pb2 + 32);
                    mma_bf16(agg[mt][0], af0, bf0[0], bf0[1]);
                    mma_bf16(agg[mt][1], af0, bf1[0], bf1[1]);
                    mma_bf16(agg[mt][0], af1, bf0[2], bf0[3]);
                    mma_bf16(agg[mt][1], af1, bf1[2], bf1[3]);
                }
                if (tl < 7) {
#pragma unroll
                    for (int j = 0; j < 4; j++) {
                        float4 v = stg[j];
                        int c = cb + ((q4 * 4 + j) << 4);
                        s0 += v.x * v.x; s1 += v.y * v.y;
                        s2 += v.z * v.z; s3 += v.w * v.w;
                        *(uint2*)(smem + xnb + c * XSTR + pq * 8) =
                            make_uint2(bf2(v.x, v.y), bf2(v.z, v.w));
                    }
                }
            }
            if (tl < 7) {
                float* sq = smf + (SM_SQ >> 2);
                sq[(pq * 4 + 0) * 17 + cb] = s0;
                sq[(pq * 4 + 1) * 17 + cb] = s1;
                sq[(pq * 4 + 2) * 17 + cb] = s2;
                sq[(pq * 4 + 3) * 17 + cb] = s3;
            }
        }
        __syncthreads();   // S3
    }

    // ---- epilogue: vlad = agg - asum*cent, intra-norm, global norm, store ----
#pragma unroll
    for (int mt = 0; mt < 4; mt++) {
        int k0 = mt * 16 + qr;
        float as0 = smf[(SM_ASUM >> 2) + k0];
        float as1 = smf[(SM_ASUM >> 2) + k0 + 8];
#pragma unroll
        for (int nt = 0; nt < 2; nt++) {
            int c0 = wp * 16 + nt * 8 + qc * 2;
            float2 ce0 = *(const float2*)(cent + k0 * CD + c0);
            float2 ce1 = *(const float2*)(cent + (k0 + 8) * CD + c0);
            agg[mt][nt][0] -= as0 * ce0.x;
            agg[mt][nt][1] -= as0 * ce0.y;
            agg[mt][nt][2] -= as1 * ce1.x;
            agg[mt][nt][3] -= as1 * ce1.y;
        }
    }
#pragma unroll
    for (int mt = 0; mt < 4; mt++) {
        float sA = 0.f, sB = 0.f;
#pragma unroll
        for (int nt = 0; nt < 2; nt++) {
            sA += agg[mt][nt][0] * agg[mt][nt][0] + agg[mt][nt][1] * agg[mt][nt][1];
            sB += agg[mt][nt][2] * agg[mt][nt][2] + agg[mt][nt][3] * agg[mt][nt][3];
        }
        sA += __shfl_xor_sync(0xffffffffu, sA, 1);
        sA += __shfl_xor_sync(0xffffffffu, sA, 2);
        sB += __shfl_xor_sync(0xffffffffu, sB, 1);
        sB += __shfl_xor_sync(0xffffffffu, sB, 2);
        if (qc == 0) {
            smf[(SM_RED >> 2) + (mt * 16 + qr) * 17 + wp] = sA;
            smf[(SM_RED >> 2) + (mt * 16 + 8 + qr) * 17 + wp] = sB;
        }
    }
    __syncthreads();
    if (t < 64) {
        float ss = 0.f;
#pragma unroll
        for (int i = 0; i < 16; i++) ss += smf[(SM_RED >> 2) + t * 17 + i];
        float dk = fmaxf(sqrtf(ss), 1e-12f);
        smf[(SM_RK >> 2) + t] = 1.0f / dk;
        float gp = ss / (dk * dk);
        gp += __shfl_xor_sync(0xffffffffu, gp, 16);
        gp += __shfl_xor_sync(0xffffffffu, gp, 8);
        gp += __shfl_xor_sync(0xffffffffu, gp, 4);
        gp += __shfl_xor_sync(0xffffffffu, gp, 2);
        gp += __shfl_xor_sync(0xffffffffu, gp, 1);
        if (lane == 0) smf[(SM_G2 >> 2) + wp] = gp;
    }
    __syncthreads();
    const float rg = 1.0f / fmaxf(sqrtf(smf[SM_G2 >> 2] + smf[(SM_G2 >> 2) + 1]), 1e-12f);
    float* on = out + (size_t)n * KK * CD;
#pragma unroll
    for (int mt = 0; mt < 4; mt++) {
        int k0 = mt * 16 + qr;
        float r0 = smf[(SM_RK >> 2) + k0] * rg;
        float r1 = smf[(SM_RK >> 2) + k0 + 8] * rg;
#pragma unroll
        for (int nt = 0; nt < 2; nt++) {
            int c0 = wp * 16 + nt * 8 + qc * 2;
            *(float2*)(on + k0 * CD + c0) =
                make_float2(agg[mt][nt][0] * r0, agg[mt][nt][1] * r0);
            *(float2*)(on + (k0 + 8) * CD + c0) =
                make_float2(agg[mt][nt][2] * r1, agg[mt][nt][3] * r1);
        }
    }
}

// ------------------------------------------------------------------------------
extern "C" void kernel_launch(void* const* d_in, const int* in_sizes, int n_in,
                              void* d_out, int out_size) {
    const float* x    = (const float*)d_in[0];  // (128, 256, 32, 32)
    const float* w    = (const float*)d_in[1];  // (64, 256)
    const float* b    = (const float*)d_in[2];  // (64)
    const float* cent = (const float*)d_in[3];  // (64, 256)
    float* out = (float*)d_out;                 // (128, 16384)

    cudaFuncSetAttribute(netvlad_mma, cudaFuncAttributeMaxDynamicSharedMemorySize, SM_TOTAL);
    netvlad_mma<<<NB, 512, SM_TOTAL>>>(x, w, b, cent, out);
}

// round 8
// speedup vs baseline: 6.7224x; 1.0322x over previous
#include <cuda_runtime.h>
#include <cuda_bf16.h>
#include <cstdint>

#define NB 128
#define CD 256
#define KK 64
#define PT 1024

// ---- smem byte offsets ----
#define SM_X0   0            // x tile bf16 [256 c][136 p] (stride 272 B), buffer 0
#define SM_X1   69632        // buffer 1
#define XSTR    272
#define SM_W    139264       // W bf16 [64 k][264 c] (stride 528 B)
#define WSTR    528
#define SM_AT   173056       // at bf16 [64 k][136 p] (stride 272 B)
#define ASTR    272
#define SM_EX   190464       // softmax exchange [128 p][4 f]
#define SM_SQ   192512       // 128 x 17 f
#define SM_RED  201216       // 64 x 33 f (asum partials) / 64 x 9 f (epilogue)
#define SM_ASUM 209664       // 64 f
#define SM_RK   209920       // 64 f
#define SM_G2   210176       // 2 f
#define SM_TOTAL 210184

__device__ __forceinline__ uint32_t smem_u32(const void* p) {
    uint32_t a;
    asm("{ .reg .u64 t; cvta.to.shared.u64 t, %1; cvt.u32.u64 %0, t; }" : "=r"(a) : "l"(p));
    return a;
}
__device__ __forceinline__ uint32_t bf2(float lo, float hi) {
    uint32_t r;
    asm("cvt.rn.bf16x2.f32 %0, %1, %2;" : "=r"(r) : "f"(hi), "f"(lo));
    return r;
}
__device__ __forceinline__ void ldm4t(uint32_t* r, uint32_t addr) {
    asm volatile("ldmatrix.sync.aligned.m8n8.x4.trans.shared.b16 {%0,%1,%2,%3}, [%4];"
                 : "=r"(r[0]), "=r"(r[1]), "=r"(r[2]), "=r"(r[3]) : "r"(addr));
}
__device__ __forceinline__ void ldm4(uint32_t* r, uint32_t addr) {
    asm volatile("ldmatrix.sync.aligned.m8n8.x4.shared.b16 {%0,%1,%2,%3}, [%4];"
                 : "=r"(r[0]), "=r"(r[1]), "=r"(r[2]), "=r"(r[3]) : "r"(addr));
}
__device__ __forceinline__ void mma_bf16(float* d, const uint32_t* a, uint32_t b0, uint32_t b1) {
    asm volatile("mma.sync.aligned.m16n8k16.row.col.f32.bf16.bf16.f32 "
                 "{%0,%1,%2,%3}, {%4,%5,%6,%7}, {%8,%9}, {%0,%1,%2,%3};"
                 : "+f"(d[0]), "+f"(d[1]), "+f"(d[2]), "+f"(d[3])
                 : "r"(a[0]), "r"(a[1]), "r"(a[2]), "r"(a[3]), "r"(b0), "r"(b1));
}
__device__ __forceinline__ void pfL2(const void* p) {
    asm volatile("prefetch.global.L2 [%0];" :: "l"(p));
}
__device__ __forceinline__ void sts16(uint32_t addr, __nv_bfloat16 v) {
    unsigned short u = *(unsigned short*)&v;
    asm volatile("st.shared.u16 [%0], %1;" :: "r"(addr), "h"(u) : "memory");
}

__global__ __launch_bounds__(512, 1) void netvlad_mma(
    const float* __restrict__ x, const float* __restrict__ w,
    const float* __restrict__ b, const float* __restrict__ cent,
    float* __restrict__ out) {
    extern __shared__ char smem[];
    float* smf = (float*)smem;
    const uint32_t sb = smem_u32(smem);
    const int t = threadIdx.x, lane = t & 31, wp = t >> 5;
    const int la = lane & 7, grp = lane >> 3, qr = lane >> 2, qc = lane & 3;
    const int mg = wp >> 1, ng = wp & 1;        // GEMM1 tiling
    const int kg = wp & 1, cg = wp >> 1;        // GEMM2 tiling (k32 x c32)
    const int n = blockIdx.x;
    const float* xn = x + (size_t)n * CD * PT;

    // ---- one-time: W -> bf16 smem, asum=0, per-lane bias regs ----
#pragma unroll
    for (int i = 0; i < 16; i++) {
        int id2 = t + (i << 9);
        int kk = id2 >> 7, c2 = id2 & 127;
        float2 v = ((const float2*)w)[id2];
        *(uint32_t*)(smem + SM_W + kk * WSTR + c2 * 4) = bf2(v.x, v.y);
    }
    if (t < KK) smf[(SM_ASUM >> 2) + t] = 0.f;
    float bsv[8];
#pragma unroll
    for (int nt = 0; nt < 4; nt++) {
        bsv[nt * 2]     = b[ng * 32 + nt * 8 + qc * 2];
        bsv[nt * 2 + 1] = b[ng * 32 + nt * 8 + qc * 2 + 1];
    }

    // ldmatrix offsets
    const uint32_t aG1off = (uint32_t)(la + ((grp >> 1) << 3)) * XSTR +
                            (uint32_t)(mg * 16 + ((grp & 1) << 3)) * 2;
    const uint32_t wG1 = sb + SM_W + (uint32_t)(ng * 32 + la) * WSTR + (uint32_t)(grp * 8) * 2;
    const uint32_t aG2 = sb + SM_AT + (uint32_t)(kg * 32 + la + ((grp & 1) << 3)) * ASTR +
                         (uint32_t)((grp >> 1) << 3) * 2;
    const uint32_t xG2off = (uint32_t)(cg * 32 + la) * XSTR + (uint32_t)(grp * 8) * 2;

    const int plo = mg * 16 + qr, phi = plo + 8;
    const int pq = t & 31, cb = t >> 5;

    float agg[2][4][4];
#pragma unroll
    for (int i = 0; i < 2; i++)
#pragma unroll
        for (int j = 0; j < 4; j++)
#pragma unroll
            for (int q = 0; q < 4; q++) agg[i][j][q] = 0.f;

    // ---- pre-loop: phase A for tile 0 into X0 ----
    {
        const float* xp = xn + pq * 4;
        float s0 = 0.f, s1 = 0.f, s2 = 0.f, s3 = 0.f;
#pragma unroll
        for (int i = 0; i < 16; i++) {
            int c = cb + (i << 4);
            float4 v = *(const float4*)(xp + (size_t)c * PT);
            s0 += v.x * v.x; s1 += v.y * v.y; s2 += v.z * v.z; s3 += v.w * v.w;
            *(uint2*)(smem + SM_X0 + c * XSTR + pq * 8) =
                make_uint2(bf2(v.x, v.y), bf2(v.z, v.w));
        }
        float* sq = smf + (SM_SQ >> 2);
        sq[(pq * 4 + 0) * 17 + cb] = s0;
        sq[(pq * 4 + 1) * 17 + cb] = s1;
        sq[(pq * 4 + 2) * 17 + cb] = s2;
        sq[(pq * 4 + 3) * 17 + cb] = s3;
    }
    __syncthreads();

    for (int tl = 0; tl < 8; tl++) {
        const uint32_t xb  = (tl & 1) ? SM_X1 : SM_X0;
        const uint32_t xnb = (tl & 1) ? SM_X0 : SM_X1;
        const uint32_t aG1 = sb + xb + aG1off;

        if (tl < 7) {
            const float* pf = xn + (size_t)(t >> 1) * PT + (tl * 128 + 128) + ((t & 1) << 6);
            pfL2(pf); pfL2(pf + 32);
        }

        // ---- GEMM1: logits[p][k], in registers ----
        float acc[4][4];
#pragma unroll
        for (int i = 0; i < 4; i++)
#pragma unroll
            for (int q = 0; q < 4; q++) acc[i][q] = 0.f;
#pragma unroll
        for (int cb32 = 0; cb32 < 256; cb32 += 32) {
            uint32_t afA[4], afB[4];
            ldm4t(afA, aG1 + (uint32_t)cb32 * XSTR);
            ldm4t(afB, aG1 + (uint32_t)(cb32 + 16) * XSTR);
#pragma unroll
            for (int nt = 0; nt < 4; nt++) {
                uint32_t wf[4];
                ldm4(wf, wG1 + (uint32_t)nt * (8 * WSTR) + (uint32_t)cb32 * 2);
                mma_bf16(acc[nt], afA, wf[0], wf[1]);
                mma_bf16(acc[nt], afB, wf[2], wf[3]);
            }
        }

        // ---- softmax part 1 ----
        float qlo = 0.f, qhi = 0.f;
#pragma unroll
        for (int i = 0; i < 4; i++) {
            qlo += smf[(SM_SQ >> 2) + plo * 17 + qc * 4 + i];
            qhi += smf[(SM_SQ >> 2) + phi * 17 + qc * 4 + i];
        }
        qlo += __shfl_xor_sync(0xffffffffu, qlo, 1);
        qlo += __shfl_xor_sync(0xffffffffu, qlo, 2);
        qhi += __shfl_xor_sync(0xffffffffu, qhi, 1);
        qhi += __shfl_xor_sync(0xffffffffu, qhi, 2);
        const float invlo = 1.0f / fmaxf(sqrtf(qlo), 1e-12f);
        const float invhi = 1.0f / fmaxf(sqrtf(qhi), 1e-12f);

        float mlo = -1e30f, mhi = -1e30f;
#pragma unroll
        for (int nt = 0; nt < 4; nt++) {
            acc[nt][0] = acc[nt][0] * invlo + bsv[nt * 2];
            acc[nt][1] = acc[nt][1] * invlo + bsv[nt * 2 + 1];
            acc[nt][2] = acc[nt][2] * invhi + bsv[nt * 2];
            acc[nt][3] = acc[nt][3] * invhi + bsv[nt * 2 + 1];
            mlo = fmaxf(mlo, fmaxf(acc[nt][0], acc[nt][1]));
            mhi = fmaxf(mhi, fmaxf(acc[nt][2], acc[nt][3]));
        }
        mlo = fmaxf(mlo, __shfl_xor_sync(0xffffffffu, mlo, 1));
        mlo = fmaxf(mlo, __shfl_xor_sync(0xffffffffu, mlo, 2));
        mhi = fmaxf(mhi, __shfl_xor_sync(0xffffffffu, mhi, 1));
        mhi = fmaxf(mhi, __shfl_xor_sync(0xffffffffu, mhi, 2));
        float slo = 0.f, shi = 0.f;
#pragma unroll
        for (int nt = 0; nt < 4; nt++) {
            acc[nt][0] = __expf(acc[nt][0] - mlo); slo += acc[nt][0];
            acc[nt][1] = __expf(acc[nt][1] - mlo); slo += acc[nt][1];
            acc[nt][2] = __expf(acc[nt][2] - mhi); shi += acc[nt][2];
            acc[nt][3] = __expf(acc[nt][3] - mhi); shi += acc[nt][3];
        }
        slo += __shfl_xor_sync(0xffffffffu, slo, 1);
        slo += __shfl_xor_sync(0xffffffffu, slo, 2);
        shi += __shfl_xor_sync(0xffffffffu, shi, 1);
        shi += __shfl_xor_sync(0xffffffffu, shi, 2);
        if (qc == 0) {
            *(float2*)(smem + SM_EX + plo * 16 + ng * 8) = make_float2(mlo, slo);
            *(float2*)(smem + SM_EX + phi * 16 + ng * 8) = make_float2(mhi, shi);
        }
        __syncthreads();   // S1

        // ---- softmax part 2: merge, direct b16 at stores, asv partials ----
        {
            float4 exl = *(float4*)(smem + SM_EX + plo * 16);
            float4 exh = *(float4*)(smem + SM_EX + phi * 16);
            float Ml = fmaxf(exl.x, exl.z), Mh = fmaxf(exh.x, exh.z);
            float Sl = exl.y * __expf(exl.x - Ml) + exl.w * __expf(exl.z - Ml);
            float Sh = exh.y * __expf(exh.x - Mh) + exh.w * __expf(exh.z - Mh);
            float scl = __expf(mlo - Ml) / Sl;
            float sch = __expf(mhi - Mh) / Sh;
            float asv[8];
            const int kb = ng * 32 + qc * 2;
#pragma unroll
            for (int nt = 0; nt < 4; nt++) {
                float a0 = acc[nt][0] * scl, a1 = acc[nt][1] * scl;
                float a2 = acc[nt][2] * sch, a3 = acc[nt][3] * sch;
                asv[nt * 2]     = a0 + a2;
                asv[nt * 2 + 1] = a1 + a3;
                int k0 = kb + nt * 8;
                uint32_t base0 = sb + SM_AT + (uint32_t)k0 * ASTR;
                sts16(base0 + (uint32_t)plo * 2, __float2bfloat16(a0 * invlo));
                sts16(base0 + ASTR + (uint32_t)plo * 2, __float2bfloat16(a1 * invlo));
                sts16(base0 + (uint32_t)phi * 2, __float2bfloat16(a2 * invhi));
                sts16(base0 + ASTR + (uint32_t)phi * 2, __float2bfloat16(a3 * invhi));
            }
#pragma unroll
            for (int j = 0; j < 8; j++)
                asv[j] += __shfl_xor_sync(0xffffffffu, asv[j], 4);
            if ((qr & 1) == 0) {
                int col = mg * 4 + (qr >> 1);
#pragma unroll
                for (int nt = 0; nt < 4; nt++) {
                    int k0 = kb + nt * 8;
                    smf[(SM_RED >> 2) + k0 * 33 + col] = asv[nt * 2];
                    smf[(SM_RED >> 2) + (k0 + 1) * 33 + col] = asv[nt * 2 + 1];
                }
            }
        }
        __syncthreads();   // S2

        // ---- asum fold + GEMM2 (k32 x c32) interleaved with phase A(tl+1) ----
        if (t < 64) {
            float s = 0.f;
#pragma unroll
            for (int i = 0; i < 32; i++) s += smf[(SM_RED >> 2) + t * 33 + i];
            smf[(SM_ASUM >> 2) + t] += s;
        }
        {
            const uint32_t xg2 = sb + xb + xG2off;
            const float* xp = xn + (tl * 128 + 128) + pq * 4;   // next tile (tl<7)
            float s0 = 0.f, s1 = 0.f, s2 = 0.f, s3 = 0.f;
#pragma unroll
            for (int q4 = 0; q4 < 4; q4++) {
                float4 stg[4];
                if (tl < 7) {
#pragma unroll
                    for (int j = 0; j < 4; j++)
                        stg[j] = *(const float4*)(xp + (size_t)(cb + ((q4 * 4 + j) << 4)) * PT);
                }
                const uint32_t pb2 = (uint32_t)(q4 * 32) * 2;
                uint32_t bfr[4][4];
#pragma unroll
                for (int nt = 0; nt < 4; nt++)
                    ldm4(bfr[nt], xg2 + (uint32_t)nt * (8 * XSTR) + pb2);
                uint32_t afr[2][2][4];
#pragma unroll
                for (int mt = 0; mt < 2; mt++) {
                    ldm4(afr[mt][0], aG2 + (uint32_t)mt * 16 * ASTR + pb2);
                    ldm4(afr[mt][1], aG2 + (uint32_t)mt * 16 * ASTR + pb2 + 32);
                }
#pragma unroll
                for (int mt = 0; mt < 2; mt++)
#pragma unroll
                    for (int nt = 0; nt < 4; nt++) {
                        mma_bf16(agg[mt][nt], afr[mt][0], bfr[nt][0], bfr[nt][1]);
                        mma_bf16(agg[mt][nt], afr[mt][1], bfr[nt][2], bfr[nt][3]);
                    }
                if (tl < 7) {
#pragma unroll
                    for (int j = 0; j < 4; j++) {
                        float4 v = stg[j];
                        int c = cb + ((q4 * 4 + j) << 4);
                        s0 += v.x * v.x; s1 += v.y * v.y;
                        s2 += v.z * v.z; s3 += v.w * v.w;
                        *(uint2*)(smem + xnb + c * XSTR + pq * 8) =
                            make_uint2(bf2(v.x, v.y), bf2(v.z, v.w));
                    }
                }
            }
            if (tl < 7) {
                float* sq = smf + (SM_SQ >> 2);
                sq[(pq * 4 + 0) * 17 + cb] = s0;
                sq[(pq * 4 + 1) * 17 + cb] = s1;
                sq[(pq * 4 + 2) * 17 + cb] = s2;
                sq[(pq * 4 + 3) * 17 + cb] = s3;
            }
        }
        __syncthreads();   // S3
    }

    // ---- epilogue: vlad = agg - asum*cent, intra-norm, global norm, store ----
#pragma unroll
    for (int mt = 0; mt < 2; mt++) {
        int kA = kg * 32 + mt * 16 + qr, kB = kA + 8;
        float as0 = smf[(SM_ASUM >> 2) + kA];
        float as1 = smf[(SM_ASUM >> 2) + kB];
#pragma unroll
        for (int nt = 0; nt < 4; nt++) {
            int c0 = cg * 32 + nt * 8 + qc * 2;
            float2 ce0 = *(const float2*)(cent + kA * CD + c0);
            float2 ce1 = *(const float2*)(cent + kB * CD + c0);
            agg[mt][nt][0] -= as0 * ce0.x;
            agg[mt][nt][1] -= as0 * ce0.y;
            agg[mt][nt][2] -= as1 * ce1.x;
            agg[mt][nt][3] -= as1 * ce1.y;
        }
    }
#pragma unroll
    for (int mt = 0; mt < 2; mt++) {
        float sA = 0.f, sB = 0.f;
#pragma unroll
        for (int nt = 0; nt < 4; nt++) {
            sA += agg[mt][nt][0] * agg[mt][nt][0] + agg[mt][nt][1] * agg[mt][nt][1];
            sB += agg[mt][nt][2] * agg[mt][nt][2] + agg[mt][nt][3] * agg[mt][nt][3];
        }
        sA += __shfl_xor_sync(0xffffffffu, sA, 1);
        sA += __shfl_xor_sync(0xffffffffu, sA, 2);
        sB += __shfl_xor_sync(0xffffffffu, sB, 1);
        sB += __shfl_xor_sync(0xffffffffu, sB, 2);
        if (qc == 0) {
            int kA = kg * 32 + mt * 16 + qr;
            smf[(SM_RED >> 2) + kA * 9 + cg] = sA;
            smf[(SM_RED >> 2) + (kA + 8) * 9 + cg] = sB;
        }
    }
    __syncthreads();
    if (t < 64) {
        float ss = 0.f;
#pragma unroll
        for (int i = 0; i < 8; i++) ss += smf[(SM_RED >> 2) + t * 9 + i];
        float dk = fmaxf(sqrtf(ss), 1e-12f);
        smf[(SM_RK >> 2) + t] = 1.0f / dk;
        float gp = ss / (dk * dk);
        gp += __shfl_xor_sync(0xffffffffu, gp, 16);
        gp += __shfl_xor_sync(0xffffffffu, gp, 8);
        gp += __shfl_xor_sync(0xffffffffu, gp, 4);
        gp += __shfl_xor_sync(0xffffffffu, gp, 2);
        gp += __shfl_xor_sync(0xffffffffu, gp, 1);
        if (lane == 0) smf[(SM_G2 >> 2) + wp] = gp;
    }
    __syncthreads();
    const float rg = 1.0f / fmaxf(sqrtf(smf[SM_G2 >> 2] + smf[(SM_G2 >> 2) + 1]), 1e-12f);
    float* on = out + (size_t)n * KK * CD;
#pragma unroll
    for (int mt = 0; mt < 2; mt++) {
        int kA = kg * 32 + mt * 16 + qr, kB = kA + 8;
        float r0 = smf[(SM_RK >> 2) + kA] * rg;
        float r1 = smf[(SM_RK >> 2) + kB] * rg;
#pragma unroll
        for (int nt = 0; nt < 4; nt++) {
            int c0 = cg * 32 + nt * 8 + qc * 2;
            *(float2*)(on + kA * CD + c0) =
                make_float2(agg[mt][nt][0] * r0, agg[mt][nt][1] * r0);
            *(float2*)(on + kB * CD + c0) =
                make_float2(agg[mt][nt][2] * r1, agg[mt][nt][3] * r1);
        }
    }
}

// ------------------------------------------------------------------------------
extern "C" void kernel_launch(void* const* d_in, const int* in_sizes, int n_in,
                              void* d_out, int out_size) {
    const float* x    = (const float*)d_in[0];  // (128, 256, 32, 32)
    const float* w    = (const float*)d_in[1];  // (64, 256)
    const float* b    = (const float*)d_in[2];  // (64)
    const float* cent = (const float*)d_in[3];  // (64, 256)
    float* out = (float*)d_out;                 // (128, 16384)

    cudaFuncSetAttribute(netvlad_mma, cudaFuncAttributeMaxDynamicSharedMemorySize, SM_TOTAL);
    netvlad_mma<<<NB, 512, SM_TOTAL>>>(x, w, b, cent, out);
}

// round 9
// speedup vs baseline: 6.9754x; 1.0376x over previous
#include <cuda_runtime.h>
#include <cuda_bf16.h>
#include <cstdint>

#define NB 128
#define CD 256
#define KK 64
#define PT 1024

// ---- smem byte offsets ----
#define SM_X0   0            // x tile bf16 [256 c][136 p] (stride 272 B)
#define SM_X1   69632
#define XSTR    272
#define SM_W    139264       // W bf16 [64 k][264 c] (stride 528 B)
#define WSTR    528
#define SM_AT   173056       // at bf16 [64 k][136 p]
#define ASTR    272
#define SM_SQ0  190464       // 128 x 17 f
#define SM_SQ1  199168       // 128 x 17 f
#define SM_RED  207872       // 64 x 33 f (asum partials) / 64 x 9 f (epilogue)
#define SM_ASUM 216320       // 64 f
#define SM_RK   216576       // 64 f
#define SM_BIAS 216832       // 64 f
#define SM_G2   217088       // 2 f
#define SM_TOTAL 217096

__device__ __forceinline__ uint32_t smem_u32(const void* p) {
    uint32_t a;
    asm("{ .reg .u64 t; cvta.to.shared.u64 t, %1; cvt.u32.u64 %0, t; }" : "=r"(a) : "l"(p));
    return a;
}
__device__ __forceinline__ uint32_t bf2(float lo, float hi) {
    uint32_t r;
    asm("cvt.rn.bf16x2.f32 %0, %1, %2;" : "=r"(r) : "f"(hi), "f"(lo));
    return r;
}
__device__ __forceinline__ void ldm4t(uint32_t* r, uint32_t addr) {
    asm volatile("ldmatrix.sync.aligned.m8n8.x4.trans.shared.b16 {%0,%1,%2,%3}, [%4];"
                 : "=r"(r[0]), "=r"(r[1]), "=r"(r[2]), "=r"(r[3]) : "r"(addr));
}
__device__ __forceinline__ void ldm4(uint32_t* r, uint32_t addr) {
    asm volatile("ldmatrix.sync.aligned.m8n8.x4.shared.b16 {%0,%1,%2,%3}, [%4];"
                 : "=r"(r[0]), "=r"(r[1]), "=r"(r[2]), "=r"(r[3]) : "r"(addr));
}
__device__ __forceinline__ void mma_bf16(float* d, const uint32_t* a, uint32_t b0, uint32_t b1) {
    asm volatile("mma.sync.aligned.m16n8k16.row.col.f32.bf16.bf16.f32 "
                 "{%0,%1,%2,%3}, {%4,%5,%6,%7}, {%8,%9}, {%0,%1,%2,%3};"
                 : "+f"(d[0]), "+f"(d[1]), "+f"(d[2]), "+f"(d[3])
                 : "r"(a[0]), "r"(a[1]), "r"(a[2]), "r"(a[3]), "r"(b0), "r"(b1));
}
__device__ __forceinline__ void sts16(uint32_t addr, __nv_bfloat16 v) {
    unsigned short u = *(unsigned short*)&v;
    asm volatile("st.shared.u16 [%0], %1;" :: "r"(addr), "h"(u) : "memory");
}

__global__ __launch_bounds__(512, 1) void netvlad_mma(
    const float* __restrict__ x, const float* __restrict__ w,
    const float* __restrict__ b, const float* __restrict__ cent,
    float* __restrict__ out) {
    extern __shared__ char smem[];
    float* smf = (float*)smem;
    const uint32_t sb = smem_u32(smem);
    const int t = threadIdx.x, lane = t & 31, wp = t >> 5;
    const int la = lane & 7, grp = lane >> 3, qr = lane >> 2, qc = lane & 3;
    const int kg = wp & 1, cg = wp >> 1;        // GEMM2 tiling (k32 x c32)
    const int n = blockIdx.x;
    const float* xn = x + (size_t)n * CD * PT;

    // ---- one-time: W -> bf16 smem, bias, asum=0 ----
#pragma unroll
    for (int i = 0; i < 16; i++) {
        int id2 = t + (i << 9);
        int kk = id2 >> 7, c2 = id2 & 127;
        float2 v = ((const float2*)w)[id2];
        *(uint32_t*)(smem + SM_W + kk * WSTR + c2 * 4) = bf2(v.x, v.y);
    }
    if (t < KK) { smf[(SM_ASUM >> 2) + t] = 0.f; smf[(SM_BIAS >> 2) + t] = b[t]; }

    // GEMM1 (warps 0-7): full k64 on 16 pixels each
    const uint32_t aG1off = (uint32_t)(la + ((grp >> 1) << 3)) * XSTR +
                            (uint32_t)(wp * 16 + ((grp & 1) << 3)) * 2;
    const uint32_t wG1 = sb + SM_W + (uint32_t)la * WSTR + (uint32_t)(grp * 8) * 2;
    // GEMM2
    const uint32_t aG2 = sb + SM_AT + (uint32_t)(kg * 32 + la + ((grp & 1) << 3)) * ASTR +
                         (uint32_t)((grp >> 1) << 3) * 2;
    const uint32_t xG2off = (uint32_t)(cg * 32 + la) * XSTR + (uint32_t)(grp * 8) * 2;

    const int plo = wp * 16 + qr, phi = plo + 8;   // GEMM1 pixel rows (warps 0-7)

    float agg[2][4][4];
#pragma unroll
    for (int i = 0; i < 2; i++)
#pragma unroll
        for (int j = 0; j < 4; j++)
#pragma unroll
            for (int q = 0; q < 4; q++) agg[i][j][q] = 0.f;

    // ---- pre-loop: tile 0 -> X0 + SQ0 (all 512 threads, 16 SQ cols) ----
    {
        const int pq = t & 31, cb = t >> 5;   // cb 0..15
        const float* xp = xn + pq * 4;
        float s0 = 0.f, s1 = 0.f, s2 = 0.f, s3 = 0.f;
#pragma unroll
        for (int i = 0; i < 16; i++) {
            int c = cb + (i << 4);
            float4 v = *(const float4*)(xp + (size_t)c * PT);
            s0 += v.x * v.x; s1 += v.y * v.y; s2 += v.z * v.z; s3 += v.w * v.w;
            *(uint2*)(smem + SM_X0 + c * XSTR + pq * 8) =
                make_uint2(bf2(v.x, v.y), bf2(v.z, v.w));
        }
        float* sq = smf + (SM_SQ0 >> 2);
        sq[(pq * 4 + 0) * 17 + cb] = s0;
        sq[(pq * 4 + 1) * 17 + cb] = s1;
        sq[(pq * 4 + 2) * 17 + cb] = s2;
        sq[(pq * 4 + 3) * 17 + cb] = s3;
    }
    __syncthreads();

    for (int tl = 0; tl < 8; tl++) {
        const uint32_t xb  = (tl & 1) ? SM_X1 : SM_X0;
        const uint32_t xnb = (tl & 1) ? SM_X0 : SM_X1;
        const uint32_t sqb = (tl & 1) ? SM_SQ1 : SM_SQ0;
        const uint32_t sqn = (tl & 1) ? SM_SQ0 : SM_SQ1;

        // ======== half 1: warps 0-7 GEMM1+softmax  |  warps 8-15 load tl+1 ========
        if (wp < 8) {
            const uint32_t aG1 = sb + xb + aG1off;
            float acc[8][4];
#pragma unroll
            for (int i = 0; i < 8; i++)
#pragma unroll
                for (int q = 0; q < 4; q++) acc[i][q] = 0.f;
#pragma unroll
            for (int cb32 = 0; cb32 < 256; cb32 += 32) {
                uint32_t afA[4], afB[4];
                ldm4t(afA, aG1 + (uint32_t)cb32 * XSTR);
                ldm4t(afB, aG1 + (uint32_t)(cb32 + 16) * XSTR);
#pragma unroll
                for (int nt = 0; nt < 8; nt++) {
                    uint32_t wf[4];
                    ldm4(wf, wG1 + (uint32_t)nt * (8 * WSTR) + (uint32_t)cb32 * 2);
                    mma_bf16(acc[nt], afA, wf[0], wf[1]);
                    mma_bf16(acc[nt], afB, wf[2], wf[3]);
                }
            }

            // warp-local softmax over k=64 (lanes: qc covers k, qr covers p)
            float qlo = 0.f, qhi = 0.f;
#pragma unroll
            for (int i = 0; i < 4; i++) {
                qlo += smf[(sqb >> 2) + plo * 17 + qc * 4 + i];
                qhi += smf[(sqb >> 2) + phi * 17 + qc * 4 + i];
            }
            qlo += __shfl_xor_sync(0xffffffffu, qlo, 1);
            qlo += __shfl_xor_sync(0xffffffffu, qlo, 2);
            qhi += __shfl_xor_sync(0xffffffffu, qhi, 1);
            qhi += __shfl_xor_sync(0xffffffffu, qhi, 2);
            const float invlo = 1.0f / fmaxf(sqrtf(qlo), 1e-12f);
            const float invhi = 1.0f / fmaxf(sqrtf(qhi), 1e-12f);

            float mlo = -1e30f, mhi = -1e30f;
#pragma unroll
            for (int nt = 0; nt < 8; nt++) {
                float b0 = smf[(SM_BIAS >> 2) + nt * 8 + qc * 2];
                float b1 = smf[(SM_BIAS >> 2) + nt * 8 + qc * 2 + 1];
                acc[nt][0] = acc[nt][0] * invlo + b0;
                acc[nt][1] = acc[nt][1] * invlo + b1;
                acc[nt][2] = acc[nt][2] * invhi + b0;
                acc[nt][3] = acc[nt][3] * invhi + b1;
                mlo = fmaxf(mlo, fmaxf(acc[nt][0], acc[nt][1]));
                mhi = fmaxf(mhi, fmaxf(acc[nt][2], acc[nt][3]));
            }
            mlo = fmaxf(mlo, __shfl_xor_sync(0xffffffffu, mlo, 1));
            mlo = fmaxf(mlo, __shfl_xor_sync(0xffffffffu, mlo, 2));
            mhi = fmaxf(mhi, __shfl_xor_sync(0xffffffffu, mhi, 1));
            mhi = fmaxf(mhi, __shfl_xor_sync(0xffffffffu, mhi, 2));
            float slo = 0.f, shi = 0.f;
#pragma unroll
            for (int nt = 0; nt < 8; nt++) {
                acc[nt][0] = __expf(acc[nt][0] - mlo); slo += acc[nt][0];
                acc[nt][1] = __expf(acc[nt][1] - mlo); slo += acc[nt][1];
                acc[nt][2] = __expf(acc[nt][2] - mhi); shi += acc[nt][2];
                acc[nt][3] = __expf(acc[nt][3] - mhi); shi += acc[nt][3];
            }
            slo += __shfl_xor_sync(0xffffffffu, slo, 1);
            slo += __shfl_xor_sync(0xffffffffu, slo, 2);
            shi += __shfl_xor_sync(0xffffffffu, shi, 1);
            shi += __shfl_xor_sync(0xffffffffu, shi, 2);
            const float rlo = 1.0f / slo, rhi = 1.0f / shi;
            const float wlo = rlo * invlo, whi = rhi * invhi;

            float asv[16];
#pragma unroll
            for (int nt = 0; nt < 8; nt++) {
                float a0 = acc[nt][0] * rlo, a1 = acc[nt][1] * rlo;
                float a2 = acc[nt][2] * rhi, a3 = acc[nt][3] * rhi;
                asv[nt * 2]     = a0 + a2;
                asv[nt * 2 + 1] = a1 + a3;
                int k0 = nt * 8 + qc * 2;
                uint32_t base0 = sb + SM_AT + (uint32_t)k0 * ASTR;
                sts16(base0 + (uint32_t)plo * 2, __float2bfloat16(acc[nt][0] * wlo));
                sts16(base0 + ASTR + (uint32_t)plo * 2, __float2bfloat16(acc[nt][1] * wlo));
                sts16(base0 + (uint32_t)phi * 2, __float2bfloat16(acc[nt][2] * whi));
                sts16(base0 + ASTR + (uint32_t)phi * 2, __float2bfloat16(acc[nt][3] * whi));
            }
#pragma unroll
            for (int j = 0; j < 16; j++)
                asv[j] += __shfl_xor_sync(0xffffffffu, asv[j], 4);
            if ((qr & 1) == 0) {
                int col = wp * 4 + (qr >> 1);
#pragma unroll
                for (int nt = 0; nt < 8; nt++) {
                    int k0 = nt * 8 + qc * 2;
                    smf[(SM_RED >> 2) + k0 * 33 + col] = asv[nt * 2];
                    smf[(SM_RED >> 2) + (k0 + 1) * 33 + col] = asv[nt * 2 + 1];
                }
            }
        } else if (tl < 7) {
            // loader warps: x(tl+1) -> other buffer, SQ partials (cols cb & cb+8)
            const int tid2 = t - 256;
            const int pq = tid2 & 31, cb = tid2 >> 5;   // cb 0..7
            const float* xp = xn + (tl * 128 + 128) + pq * 4;
            float sA0 = 0.f, sA1 = 0.f, sA2 = 0.f, sA3 = 0.f;
            float sB0 = 0.f, sB1 = 0.f, sB2 = 0.f, sB3 = 0.f;
#pragma unroll
            for (int i = 0; i < 16; i++) {
                int c = cb + (i << 3);
                float4 v = *(const float4*)(xp + (size_t)c * PT);
                sA0 += v.x * v.x; sA1 += v.y * v.y; sA2 += v.z * v.z; sA3 += v.w * v.w;
                *(uint2*)(smem + xnb + c * XSTR + pq * 8) =
                    make_uint2(bf2(v.x, v.y), bf2(v.z, v.w));
            }
#pragma unroll
            for (int i = 16; i < 32; i++) {
                int c = cb + (i << 3);
                float4 v = *(const float4*)(xp + (size_t)c * PT);
                sB0 += v.x * v.x; sB1 += v.y * v.y; sB2 += v.z * v.z; sB3 += v.w * v.w;
                *(uint2*)(smem + xnb + c * XSTR + pq * 8) =
                    make_uint2(bf2(v.x, v.y), bf2(v.z, v.w));
            }
            float* sq = smf + (sqn >> 2);
            sq[(pq * 4 + 0) * 17 + cb] = sA0;
            sq[(pq * 4 + 1) * 17 + cb] = sA1;
            sq[(pq * 4 + 2) * 17 + cb] = sA2;
            sq[(pq * 4 + 3) * 17 + cb] = sA3;
            sq[(pq * 4 + 0) * 17 + cb + 8] = sB0;
            sq[(pq * 4 + 1) * 17 + cb + 8] = sB1;
            sq[(pq * 4 + 2) * 17 + cb + 8] = sB2;
            sq[(pq * 4 + 3) * 17 + cb + 8] = sB3;
        }
        __syncthreads();   // S1

        // ======== half 2: asum fold + GEMM2 (all 16 warps) ========
        if (t < 64) {
            float s = 0.f;
#pragma unroll
            for (int i = 0; i < 32; i++) s += smf[(SM_RED >> 2) + t * 33 + i];
            smf[(SM_ASUM >> 2) + t] += s;
        }
        {
            const uint32_t xg2 = sb + xb + xG2off;
#pragma unroll
            for (int q4 = 0; q4 < 4; q4++) {
                const uint32_t pb2 = (uint32_t)(q4 * 32) * 2;
                uint32_t bfr[4][4];
#pragma unroll
                for (int nt = 0; nt < 4; nt++)
                    ldm4(bfr[nt], xg2 + (uint32_t)nt * (8 * XSTR) + pb2);
                uint32_t afr[2][2][4];
#pragma unroll
                for (int mt = 0; mt < 2; mt++) {
                    ldm4(afr[mt][0], aG2 + (uint32_t)mt * 16 * ASTR + pb2);
                    ldm4(afr[mt][1], aG2 + (uint32_t)mt * 16 * ASTR + pb2 + 32);
                }
#pragma unroll
                for (int mt = 0; mt < 2; mt++)
#pragma unroll
                    for (int nt = 0; nt < 4; nt++) {
                        mma_bf16(agg[mt][nt], afr[mt][0], bfr[nt][0], bfr[nt][1]);
                        mma_bf16(agg[mt][nt], afr[mt][1], bfr[nt][2], bfr[nt][3]);
                    }
            }
        }
        __syncthreads();   // S2
    }

    // ---- epilogue: vlad = agg - asum*cent, intra-norm, global norm, store ----
#pragma unroll
    for (int mt = 0; mt < 2; mt++) {
        int kA = kg * 32 + mt * 16 + qr, kB = kA + 8;
        float as0 = smf[(SM_ASUM >> 2) + kA];
        float as1 = smf[(SM_ASUM >> 2) + kB];
#pragma unroll
        for (int nt = 0; nt < 4; nt++) {
            int c0 = cg * 32 + nt * 8 + qc * 2;
            float2 ce0 = *(const float2*)(cent + kA * CD + c0);
            float2 ce1 = *(const float2*)(cent + kB * CD + c0);
            agg[mt][nt][0] -= as0 * ce0.x;
            agg[mt][nt][1] -= as0 * ce0.y;
            agg[mt][nt][2] -= as1 * ce1.x;
            agg[mt][nt][3] -= as1 * ce1.y;
        }
    }
#pragma unroll
    for (int mt = 0; mt < 2; mt++) {
        float sA = 0.f, sB = 0.f;
#pragma unroll
        for (int nt = 0; nt < 4; nt++) {
            sA += agg[mt][nt][0] * agg[mt][nt][0] + agg[mt][nt][1] * agg[mt][nt][1];
            sB += agg[mt][nt][2] * agg[mt][nt][2] + agg[mt][nt][3] * agg[mt][nt][3];
        }
        sA += __shfl_xor_sync(0xffffffffu, sA, 1);
        sA += __shfl_xor_sync(0xffffffffu, sA, 2);
        sB += __shfl_xor_sync(0xffffffffu, sB, 1);
        sB += __shfl_xor_sync(0xffffffffu, sB, 2);
        if (qc == 0) {
            int kA = kg * 32 + mt * 16 + qr;
            smf[(SM_RED >> 2) + kA * 9 + cg] = sA;
            smf[(SM_RED >> 2) + (kA + 8) * 9 + cg] = sB;
        }
    }
    __syncthreads();
    if (t < 64) {
        float ss = 0.f;
#pragma unroll
        for (int i = 0; i < 8; i++) ss += smf[(SM_RED >> 2) + t * 9 + i];
        float dk = fmaxf(sqrtf(ss), 1e-12f);
        smf[(SM_RK >> 2) + t] = 1.0f / dk;
        float gp = ss / (dk * dk);
        gp += __shfl_xor_sync(0xffffffffu, gp, 16);
        gp += __shfl_xor_sync(0xffffffffu, gp, 8);
        gp += __shfl_xor_sync(0xffffffffu, gp, 4);
        gp += __shfl_xor_sync(0xffffffffu, gp, 2);
        gp += __shfl_xor_sync(0xffffffffu, gp, 1);
        if (lane == 0) smf[(SM_G2 >> 2) + wp] = gp;
    }
    __syncthreads();
    const float rg = 1.0f / fmaxf(sqrtf(smf[SM_G2 >> 2] + smf[(SM_G2 >> 2) + 1]), 1e-12f);
    float* on = out + (size_t)n * KK * CD;
#pragma unroll
    for (int mt = 0; mt < 2; mt++) {
        int kA = kg * 32 + mt * 16 + qr, kB = kA + 8;
        float r0 = smf[(SM_RK >> 2) + kA] * rg;
        float r1 = smf[(SM_RK >> 2) + kB] * rg;
#pragma unroll
        for (int nt = 0; nt < 4; nt++) {
            int c0 = cg * 32 + nt * 8 + qc * 2;
            *(float2*)(on + kA * CD + c0) =
                make_float2(agg[mt][nt][0] * r0, agg[mt][nt][1] * r0);
            *(float2*)(on + kB * CD + c0) =
                make_float2(agg[mt][nt][2] * r1, agg[mt][nt][3] * r1);
        }
    }
}

// ------------------------------------------------------------------------------
extern "C" void kernel_launch(void* const* d_in, const int* in_sizes, int n_in,
                              void* d_out, int out_size) {
    const float* x    = (const float*)d_in[0];  // (128, 256, 32, 32)
    const float* w    = (const float*)d_in[1];  // (64, 256)
    const float* b    = (const float*)d_in[2];  // (64)
    const float* cent = (const float*)d_in[3];  // (64, 256)
    float* out = (float*)d_out;                 // (128, 16384)

    cudaFuncSetAttribute(netvlad_mma, cudaFuncAttributeMaxDynamicSharedMemorySize, SM_TOTAL);
    netvlad_mma<<<NB, 512, SM_TOTAL>>>(x, w, b, cent, out);
}